// round 1
// baseline (speedup 1.0000x reference)
#include <cuda_runtime.h>
#include <math.h>

// ---------------------------------------------------------------------------
// Decomposable-Attention NLI forward, fp32 baseline.
// B=32, L=256, D=1024, ALIGN=1024, FF=2048, NUM_CLASSES=3
//
// Pipeline:
//  1) Fp = tanh(P @ W_F)   [8192,1024]   2) Fh = tanh(H @ W_F)
//  3) E[b] = Fp[b] @ Fh[b]^T  [256,256]  4) softmax rows (in place -> attn)
//  5) betas[b]  = attn[b]   @ H[b]
//  6) alphas[b] = attn[b]^T @ P[b]
//  7) S1[b] = sum_p tanh([P|betas][b,p,:] @ W_G)   (fused GEMM+tanh+rowsum)
//  8) S2[b] = sum_h tanh([H|alphas][b,h,:] @ W_G)
//  9) a1 = tanh([S1|S2] @ W1 + b1); 10) a2 = tanh(a1 @ W2 + b2)
// 11) logits = a2 @ W3 + b3  -> d_out [32,3]
// ---------------------------------------------------------------------------

#define BB 32
#define LL 256
#define DD 1024
#define FFDIM 2048

// scratch layout (floats)
#define OFF_FP     0L
#define OFF_FH     (OFF_FP + 32L*256*1024)
#define OFF_ATTN   (OFF_FH + 32L*256*1024)
#define OFF_BETA   (OFF_ATTN + 32L*256*256)
#define OFF_ALPHA  (OFF_BETA + 32L*256*1024)
#define OFF_S1     (OFF_ALPHA + 32L*256*1024)
#define OFF_S2     (OFF_S1 + 32L*2048)
#define OFF_A1     (OFF_S2 + 32L*2048)
#define OFF_A2     (OFF_A1 + 32L*2048)
#define SCRATCH_ELEMS (OFF_A2 + 32L*2048)

__device__ __align__(256) float g_scratch[SCRATCH_ELEMS];

// ---------------------------------------------------------------------------
// Generic tiled SGEMM: C = op(A) @ op(B), optionally tanh epilogue.
// TRANS_A: A is [K,M] row-major (we compute A^T@B). else A is [M,K].
// TRANS_B: B is [N,K] row-major (we compute A@B^T). else B is [K,N].
// All of M,N multiples of 128, K multiple of 8. Batched via blockIdx.z.
// Tile 128x128x8, 256 threads, 8x8 microtile.
// ---------------------------------------------------------------------------
template <int TRANS_A, int TRANS_B, int DO_TANH>
__global__ __launch_bounds__(256) void sgemm_kernel(
    const float* __restrict__ A, const float* __restrict__ B,
    float* __restrict__ C, int M, int N, int K,
    long strideA, long strideB, long strideC)
{
    A += blockIdx.z * strideA;
    B += blockIdx.z * strideB;
    C += blockIdx.z * strideC;

    const int bm = blockIdx.y * 128;
    const int bn = blockIdx.x * 128;
    const int tid = threadIdx.x;
    const int tx = tid & 15;
    const int ty = tid >> 4;

    __shared__ float As[8][128];
    __shared__ float Bs[8][128];

    float acc[8][8];
#pragma unroll
    for (int i = 0; i < 8; i++)
#pragma unroll
        for (int j = 0; j < 8; j++) acc[i][j] = 0.f;

    for (int k0 = 0; k0 < K; k0 += 8) {
        if (!TRANS_A) {
            const int row = tid >> 1;
            const int kc = (tid & 1) * 4;
            float4 v = *(const float4*)&A[(long)(bm + row) * K + k0 + kc];
            As[kc + 0][row] = v.x; As[kc + 1][row] = v.y;
            As[kc + 2][row] = v.z; As[kc + 3][row] = v.w;
        } else {
            const int idx = tid * 4;
            const int kk = idx >> 7;
            const int mm = idx & 127;
            float4 v = *(const float4*)&A[(long)(k0 + kk) * M + bm + mm];
            *(float4*)&As[kk][mm] = v;
        }
        if (!TRANS_B) {
            const int idx = tid * 4;
            const int kk = idx >> 7;
            const int nn = idx & 127;
            float4 v = *(const float4*)&B[(long)(k0 + kk) * N + bn + nn];
            *(float4*)&Bs[kk][nn] = v;
        } else {
            const int row = tid >> 1;
            const int kc = (tid & 1) * 4;
            float4 v = *(const float4*)&B[(long)(bn + row) * K + k0 + kc];
            Bs[kc + 0][row] = v.x; Bs[kc + 1][row] = v.y;
            Bs[kc + 2][row] = v.z; Bs[kc + 3][row] = v.w;
        }
        __syncthreads();
#pragma unroll
        for (int kk = 0; kk < 8; kk++) {
            float a[8], b[8];
            *(float4*)&a[0] = *(const float4*)&As[kk][ty * 4];
            *(float4*)&a[4] = *(const float4*)&As[kk][64 + ty * 4];
            *(float4*)&b[0] = *(const float4*)&Bs[kk][tx * 4];
            *(float4*)&b[4] = *(const float4*)&Bs[kk][64 + tx * 4];
#pragma unroll
            for (int i = 0; i < 8; i++)
#pragma unroll
                for (int j = 0; j < 8; j++) acc[i][j] += a[i] * b[j];
        }
        __syncthreads();
    }

#pragma unroll
    for (int i = 0; i < 8; i++) {
        const int mi = (i < 4) ? (ty * 4 + i) : (64 + ty * 4 + i - 4);
        const long rowoff = (long)(bm + mi) * N + bn;
        float4 v0 = make_float4(acc[i][0], acc[i][1], acc[i][2], acc[i][3]);
        float4 v1 = make_float4(acc[i][4], acc[i][5], acc[i][6], acc[i][7]);
        if (DO_TANH) {
            v0.x = tanhf(v0.x); v0.y = tanhf(v0.y); v0.z = tanhf(v0.z); v0.w = tanhf(v0.w);
            v1.x = tanhf(v1.x); v1.y = tanhf(v1.y); v1.z = tanhf(v1.z); v1.w = tanhf(v1.w);
        }
        *(float4*)&C[rowoff + tx * 4] = v0;
        *(float4*)&C[rowoff + 64 + tx * 4] = v1;
    }
}

// ---------------------------------------------------------------------------
// Row softmax over 256 columns, in place. One warp per row.
// ---------------------------------------------------------------------------
__global__ void softmax256_kernel(float* __restrict__ E)
{
    const long row = (long)blockIdx.x * 8 + threadIdx.y;
    float* r = E + row * 256;
    const int lane = threadIdx.x;

    float v[8];
    float mx = -1e30f;
#pragma unroll
    for (int i = 0; i < 8; i++) {
        v[i] = r[i * 32 + lane];
        mx = fmaxf(mx, v[i]);
    }
#pragma unroll
    for (int o = 16; o; o >>= 1) mx = fmaxf(mx, __shfl_xor_sync(0xffffffffu, mx, o));
    float s = 0.f;
#pragma unroll
    for (int i = 0; i < 8; i++) {
        v[i] = expf(v[i] - mx);
        s += v[i];
    }
#pragma unroll
    for (int o = 16; o; o >>= 1) s += __shfl_xor_sync(0xffffffffu, s, o);
    const float inv = 1.0f / s;
#pragma unroll
    for (int i = 0; i < 8; i++) r[i * 32 + lane] = v[i] * inv;
}

// ---------------------------------------------------------------------------
// Fused compare stage: out[b,n] = sum_{p<256} tanh( concat(X1[b,p,:],X2[b,p,:]) @ W[:,n] )
// X1,X2: [B,256,1024]; W: [2048,2048]; out: [B,2048]
// One block handles (b, 128-wide n tile); loops over the two 128-row p tiles.
// ---------------------------------------------------------------------------
__global__ __launch_bounds__(256) void compare_sum_kernel(
    const float* __restrict__ X1, const float* __restrict__ X2,
    const float* __restrict__ W, float* __restrict__ out)
{
    const int b = blockIdx.z;
    X1 += (long)b * 256 * 1024;
    X2 += (long)b * 256 * 1024;
    const int bn = blockIdx.x * 128;

    const int tid = threadIdx.x;
    const int tx = tid & 15;
    const int ty = tid >> 4;

    __shared__ float As[8][128];
    __shared__ float Bs[8][128];
    __shared__ float red[16][128];

    float csum[8];
#pragma unroll
    for (int j = 0; j < 8; j++) csum[j] = 0.f;

    for (int mt = 0; mt < 256; mt += 128) {
        float acc[8][8];
#pragma unroll
        for (int i = 0; i < 8; i++)
#pragma unroll
            for (int j = 0; j < 8; j++) acc[i][j] = 0.f;

        for (int k0 = 0; k0 < 2048; k0 += 8) {
            // A: concat(X1,X2) rows mt..mt+127, cols k0..k0+7
            {
                const int row = tid >> 1;
                const int kc = (tid & 1) * 4;
                const int k = k0 + kc;
                const float* src = (k < 1024)
                    ? &X1[(long)(mt + row) * 1024 + k]
                    : &X2[(long)(mt + row) * 1024 + (k - 1024)];
                float4 v = *(const float4*)src;
                As[kc + 0][row] = v.x; As[kc + 1][row] = v.y;
                As[kc + 2][row] = v.z; As[kc + 3][row] = v.w;
            }
            // B: W[k][n]
            {
                const int idx = tid * 4;
                const int kk = idx >> 7;
                const int nn = idx & 127;
                float4 v = *(const float4*)&W[(long)(k0 + kk) * 2048 + bn + nn];
                *(float4*)&Bs[kk][nn] = v;
            }
            __syncthreads();
#pragma unroll
            for (int kk = 0; kk < 8; kk++) {
                float a[8], bq[8];
                *(float4*)&a[0] = *(const float4*)&As[kk][ty * 4];
                *(float4*)&a[4] = *(const float4*)&As[kk][64 + ty * 4];
                *(float4*)&bq[0] = *(const float4*)&Bs[kk][tx * 4];
                *(float4*)&bq[4] = *(const float4*)&Bs[kk][64 + tx * 4];
#pragma unroll
                for (int i = 0; i < 8; i++)
#pragma unroll
                    for (int j = 0; j < 8; j++) acc[i][j] += a[i] * bq[j];
            }
            __syncthreads();
        }
        // tanh + accumulate row-sum (rows are summed out, columns kept)
#pragma unroll
        for (int i = 0; i < 8; i++)
#pragma unroll
            for (int j = 0; j < 8; j++) csum[j] += tanhf(acc[i][j]);
    }

    // cross-thread reduction over the 16 ty groups
#pragma unroll
    for (int j = 0; j < 4; j++) red[ty][tx * 4 + j] = csum[j];
#pragma unroll
    for (int j = 4; j < 8; j++) red[ty][64 + tx * 4 + (j - 4)] = csum[j];
    __syncthreads();
    if (tid < 128) {
        float s = 0.f;
#pragma unroll
        for (int r = 0; r < 16; r++) s += red[r][tid];
        out[(long)b * 2048 + bn + tid] = s;
    }
}

// ---------------------------------------------------------------------------
// Skinny MLP layer: out[m,n] = act( concat(A1,A2)[m,:] @ W[:,n] + bias[n] )
// M=32 rows total; grid.y splits M into groups of 8; 128 threads = 128 n cols.
// A[m][k] = (k < ksplit) ? A1[m*ksplit + k] : A2[m*ksplit + (k-ksplit)]
// ---------------------------------------------------------------------------
__global__ __launch_bounds__(128) void mlp_layer_kernel(
    const float* __restrict__ A1, const float* __restrict__ A2, int ksplit,
    const float* __restrict__ W, const float* __restrict__ bias,
    float* __restrict__ out, int N, int K, int do_tanh)
{
    const int n = blockIdx.x * 128 + threadIdx.x;
    const int m0 = blockIdx.y * 8;

    __shared__ float As[8][129];
    float acc[8];
#pragma unroll
    for (int i = 0; i < 8; i++) acc[i] = 0.f;

    for (int k0 = 0; k0 < K; k0 += 128) {
#pragma unroll
        for (int i = 0; i < 8; i++) {
            const int k = k0 + threadIdx.x;
            As[i][threadIdx.x] = (k < ksplit)
                ? A1[(long)(m0 + i) * ksplit + k]
                : A2[(long)(m0 + i) * ksplit + (k - ksplit)];
        }
        __syncthreads();
        for (int kk = 0; kk < 128; kk++) {
            const float w = W[(long)(k0 + kk) * N + n];
#pragma unroll
            for (int i = 0; i < 8; i++) acc[i] += As[i][kk] * w;
        }
        __syncthreads();
    }
    const float bb = bias[n];
#pragma unroll
    for (int i = 0; i < 8; i++) {
        float r = acc[i] + bb;
        out[(long)(m0 + i) * N + n] = do_tanh ? tanhf(r) : r;
    }
}

// ---------------------------------------------------------------------------
// Final tiny layer: logits[m,n] = A[m,:] @ W3[:,n] + b3[n]; [32,2048]@[2048,3]
// One warp per output element.
// ---------------------------------------------------------------------------
__global__ void final_layer_kernel(
    const float* __restrict__ A, const float* __restrict__ W3,
    const float* __restrict__ b3, float* __restrict__ out)
{
    const int m = blockIdx.x / 3;
    const int n = blockIdx.x % 3;
    const int lane = threadIdx.x;
    float s = 0.f;
    for (int k = lane; k < 2048; k += 32)
        s += A[(long)m * 2048 + k] * W3[(long)k * 3 + n];
#pragma unroll
    for (int o = 16; o; o >>= 1) s += __shfl_xor_sync(0xffffffffu, s, o);
    if (lane == 0) out[m * 3 + n] = s + b3[n];
}

// ---------------------------------------------------------------------------
extern "C" void kernel_launch(void* const* d_in, const int* in_sizes, int n_in,
                              void* d_out, int out_size)
{
    const float* premises   = (const float*)d_in[0];
    const float* hypotheses = (const float*)d_in[1];
    const float* W_F = (const float*)d_in[2];
    const float* W_G = (const float*)d_in[3];
    const float* W1  = (const float*)d_in[4];
    const float* b1  = (const float*)d_in[5];
    const float* W2  = (const float*)d_in[6];
    const float* b2  = (const float*)d_in[7];
    const float* W3  = (const float*)d_in[8];
    const float* b3  = (const float*)d_in[9];
    float* out = (float*)d_out;

    float* scratch = nullptr;
    cudaGetSymbolAddress((void**)&scratch, g_scratch);

    float* Fp    = scratch + OFF_FP;
    float* Fh    = scratch + OFF_FH;
    float* attn  = scratch + OFF_ATTN;
    float* betas = scratch + OFF_BETA;
    float* alphas = scratch + OFF_ALPHA;
    float* S1    = scratch + OFF_S1;
    float* S2    = scratch + OFF_S2;
    float* a1    = scratch + OFF_A1;
    float* a2    = scratch + OFF_A2;

    // 1,2) projections + tanh: [8192,1024] @ [1024,1024]
    {
        dim3 g(1024 / 128, 8192 / 128, 1);
        sgemm_kernel<0, 0, 1><<<g, 256>>>(premises, W_F, Fp, 8192, 1024, 1024, 0, 0, 0);
        sgemm_kernel<0, 0, 1><<<g, 256>>>(hypotheses, W_F, Fh, 8192, 1024, 1024, 0, 0, 0);
    }
    // 3) E[b] = Fp[b] @ Fh[b]^T
    {
        dim3 g(2, 2, 32);
        sgemm_kernel<0, 1, 0><<<g, 256>>>(Fp, Fh, attn, 256, 256, 1024,
                                          256L * 1024, 256L * 1024, 256L * 256);
    }
    // 4) softmax rows
    softmax256_kernel<<<1024, dim3(32, 8)>>>(attn);
    // 5) betas[b] = attn[b] @ H[b]
    {
        dim3 g(8, 2, 32);
        sgemm_kernel<0, 0, 0><<<g, 256>>>(attn, hypotheses, betas, 256, 1024, 256,
                                          256L * 256, 256L * 1024, 256L * 1024);
        // 6) alphas[b] = attn[b]^T @ P[b]
        sgemm_kernel<1, 0, 0><<<g, 256>>>(attn, premises, alphas, 256, 1024, 256,
                                          256L * 256, 256L * 1024, 256L * 1024);
    }
    // 7,8) compare (fused GEMM + tanh + sequence-sum)
    {
        dim3 g(2048 / 128, 1, 32);
        compare_sum_kernel<<<g, 256>>>(premises, betas, W_G, S1);
        compare_sum_kernel<<<g, 256>>>(hypotheses, alphas, W_G, S2);
    }
    // 9) a1 = tanh([S1|S2] @ W1 + b1)
    mlp_layer_kernel<<<dim3(2048 / 128, 4), 128>>>(S1, S2, 2048, W1, b1, a1, 2048, 4096, 1);
    // 10) a2 = tanh(a1 @ W2 + b2)
    mlp_layer_kernel<<<dim3(2048 / 128, 4), 128>>>(a1, a1, 2048, W2, b2, a2, 2048, 2048, 1);
    // 11) logits
    final_layer_kernel<<<96, 32>>>(a2, W3, b3, out);
}

// round 4
// speedup vs baseline: 1.5520x; 1.5520x over previous
#include <cuda_runtime.h>
#include <math.h>

// ---------------------------------------------------------------------------
// Decomposable-Attention NLI forward.
// GEMMs on tensor cores via bf16-split (hi/lo) mma.sync.m16n8k16, fp32 accum:
//   A@B ~= Ah@Bh + Ah@Bl + Al@Bh   (error ~2^-16, fp32-class end to end)
// B=32, L=256, D=1024, FF=2048.
// ---------------------------------------------------------------------------

#define OFF_FP     0L
#define OFF_FH     (OFF_FP + 32L*256*1024)
#define OFF_ATTN   (OFF_FH + 32L*256*1024)
#define OFF_BETA   (OFF_ATTN + 32L*256*256)
#define OFF_ALPHA  (OFF_BETA + 32L*256*1024)
#define OFF_S1     (OFF_ALPHA + 32L*256*1024)
#define OFF_S2     (OFF_S1 + 32L*2048)
#define OFF_A1     (OFF_S2 + 32L*2048)
#define OFF_A2     (OFF_A1 + 32L*2048)
#define SCRATCH_ELEMS (OFF_A2 + 32L*2048)

__device__ __align__(256) float g_scratch[SCRATCH_ELEMS];

// Swizzled smem word layout for a 16(kpair) x 128(m/n) tile of bf16x2 words.
// Conflict-free for both store patterns and all m16n8k16 fragment loads.
__device__ __forceinline__ int swz(int kp, int m) {
    return (kp << 7) + (m ^ ((8 * (kp & 3)) ^ (4 * ((kp >> 2) & 7))));
}

// Split two k-consecutive floats into packed bf16x2 hi and lo words.
// Word layout: low 16 bits = even k, high 16 bits = odd k (mma frag order).
__device__ __forceinline__ void split2(float v0, float v1, unsigned& hi, unsigned& lo) {
    unsigned h;
    asm("cvt.rn.bf16x2.f32 %0, %1, %2;" : "=r"(h) : "f"(v1), "f"(v0));
    float h0 = __uint_as_float(h << 16);
    float h1 = __uint_as_float(h & 0xFFFF0000u);
    float r0 = v0 - h0;
    float r1 = v1 - h1;
    asm("cvt.rn.bf16x2.f32 %0, %1, %2;" : "=r"(lo) : "f"(r1), "f"(r0));
    hi = h;
}

__device__ __forceinline__ void mma_bf16(float* c, const unsigned* a, const unsigned* b) {
    asm volatile(
        "mma.sync.aligned.m16n8k16.row.col.f32.bf16.bf16.f32 "
        "{%0,%1,%2,%3},{%4,%5,%6,%7},{%8,%9},{%0,%1,%2,%3};\n"
        : "+f"(c[0]), "+f"(c[1]), "+f"(c[2]), "+f"(c[3])
        : "r"(a[0]), "r"(a[1]), "r"(a[2]), "r"(a[3]), "r"(b[0]), "r"(b[1]));
}

// gmem tile: 32 K rows (stride ld), 128 contiguous M/N cols. Packs k-pairs.
__device__ __forceinline__ void load_direct(unsigned* Shi, unsigned* Slo,
                                            const float* src, long ld, int t) {
#pragma unroll
    for (int i = 0; i < 2; i++) {
        const int kp = (t >> 5) + (i << 3);
        const int n = (t & 31) << 2;
        float4 v0 = *(const float4*)(src + (long)(2 * kp) * ld + n);
        float4 v1 = *(const float4*)(src + (long)(2 * kp + 1) * ld + n);
        unsigned h[4], l[4];
        split2(v0.x, v1.x, h[0], l[0]);
        split2(v0.y, v1.y, h[1], l[1]);
        split2(v0.z, v1.z, h[2], l[2]);
        split2(v0.w, v1.w, h[3], l[3]);
        const int gk = (8 * (kp & 3)) ^ (4 * ((kp >> 2) & 7));
        const int idx = (kp << 7) + (n ^ gk);  // gk is a multiple of 4: 4 words stay consecutive
        *(uint4*)&Shi[idx] = make_uint4(h[0], h[1], h[2], h[3]);
        *(uint4*)&Slo[idx] = make_uint4(l[0], l[1], l[2], l[3]);
    }
}

// gmem tile: 128 M/N rows (stride ld), 32 contiguous K cols.
__device__ __forceinline__ void load_trans(unsigned* Shi, unsigned* Slo,
                                           const float* src, long ld, int t) {
#pragma unroll
    for (int i = 0; i < 4; i++) {
        const int m = (t >> 3) + (i << 5);
        const int kc = (t & 7) << 2;
        float4 v = *(const float4*)(src + (long)m * ld + kc);
        unsigned h0, l0, h1, l1;
        split2(v.x, v.y, h0, l0);
        split2(v.z, v.w, h1, l1);
        const int kp = kc >> 1;
        Shi[swz(kp, m)] = h0;     Slo[swz(kp, m)] = l0;
        Shi[swz(kp + 1, m)] = h1; Slo[swz(kp + 1, m)] = l1;
    }
}

// per-warp compute over a staged 32-deep K tile (2 x k16 steps, 3 mma each)
__device__ __forceinline__ void warp_compute(
    const unsigned* Ah, const unsigned* Al, const unsigned* Bh, const unsigned* Bl,
    float acc[4][4][4], int wm, int wn, int lane)
{
    const int c = lane & 3, r = lane >> 2;
#pragma unroll
    for (int s = 0; s < 2; s++) {
        const int kpa = 8 * s + c, kpb = kpa + 4;
        unsigned bh[4][2], bl[4][2];
#pragma unroll
        for (int nf = 0; nf < 4; nf++) {
            const int n = wn * 32 + nf * 8 + r;
            bh[nf][0] = Bh[swz(kpa, n)]; bh[nf][1] = Bh[swz(kpb, n)];
            bl[nf][0] = Bl[swz(kpa, n)]; bl[nf][1] = Bl[swz(kpb, n)];
        }
#pragma unroll
        for (int mf = 0; mf < 4; mf++) {
            const int m = wm * 64 + mf * 16 + r;
            unsigned ah[4], al[4];
            ah[0] = Ah[swz(kpa, m)]; ah[1] = Ah[swz(kpa, m + 8)];
            ah[2] = Ah[swz(kpb, m)]; ah[3] = Ah[swz(kpb, m + 8)];
            al[0] = Al[swz(kpa, m)]; al[1] = Al[swz(kpa, m + 8)];
            al[2] = Al[swz(kpb, m)]; al[3] = Al[swz(kpb, m + 8)];
#pragma unroll
            for (int nf = 0; nf < 4; nf++) {
                mma_bf16(acc[mf][nf], ah, bh[nf]);
                mma_bf16(acc[mf][nf], ah, bl[nf]);
                mma_bf16(acc[mf][nf], al, bh[nf]);
            }
        }
    }
}

// ---------------------------------------------------------------------------
// Generic split-bf16 GEMM. A_TL: A gmem is [M][K] (load_trans), else [K][M].
// B_TL: B gmem is [N][K] (load_trans), else [K][N]. C = A@B (math), [M][N].
// M,N mult of 128, K mult of 32. Batched via blockIdx.z.
// ---------------------------------------------------------------------------
template <int A_TL, int B_TL, int DO_TANH>
__global__ __launch_bounds__(256, 2) void split_gemm(
    const float* __restrict__ A, const float* __restrict__ B, float* __restrict__ C,
    int M, int N, int K, long lda, long ldb, long sA, long sB, long sC)
{
    A += blockIdx.z * sA;
    B += blockIdx.z * sB;
    C += blockIdx.z * sC;

    __shared__ __align__(16) unsigned Ah[16 * 128], Al[16 * 128];
    __shared__ __align__(16) unsigned Bh[16 * 128], Bl[16 * 128];

    const int t = threadIdx.x, lane = t & 31, w = t >> 5;
    const int wm = w >> 2, wn = w & 3;
    const int bm = blockIdx.y * 128, bn = blockIdx.x * 128;

    float acc[4][4][4];
#pragma unroll
    for (int i = 0; i < 4; i++)
#pragma unroll
        for (int j = 0; j < 4; j++)
#pragma unroll
            for (int q = 0; q < 4; q++) acc[i][j][q] = 0.f;

    for (int k0 = 0; k0 < K; k0 += 32) {
        if (A_TL) load_trans(Ah, Al, A + (long)bm * lda + k0, lda, t);
        else      load_direct(Ah, Al, A + (long)k0 * lda + bm, lda, t);
        if (B_TL) load_trans(Bh, Bl, B + (long)bn * ldb + k0, ldb, t);
        else      load_direct(Bh, Bl, B + (long)k0 * ldb + bn, ldb, t);
        __syncthreads();
        warp_compute(Ah, Al, Bh, Bl, acc, wm, wn, lane);
        __syncthreads();
    }

    const int r = lane >> 2, c2 = (lane & 3) * 2;
#pragma unroll
    for (int mf = 0; mf < 4; mf++)
#pragma unroll
        for (int nf = 0; nf < 4; nf++) {
            const int row = bm + wm * 64 + mf * 16 + r;
            const int col = bn + wn * 32 + nf * 8 + c2;
            float2 v0 = make_float2(acc[mf][nf][0], acc[mf][nf][1]);
            float2 v1 = make_float2(acc[mf][nf][2], acc[mf][nf][3]);
            if (DO_TANH) {
                v0.x = tanhf(v0.x); v0.y = tanhf(v0.y);
                v1.x = tanhf(v1.x); v1.y = tanhf(v1.y);
            }
            *(float2*)&C[(long)row * N + col] = v0;
            *(float2*)&C[(long)(row + 8) * N + col] = v1;
        }
}

// ---------------------------------------------------------------------------
// Fused compare: out[b,n] = sum_{p<256} tanh( concat(X1,X2)[b,p,:] @ W[:,n] )
// ---------------------------------------------------------------------------
__global__ __launch_bounds__(256, 2) void compare_split(
    const float* __restrict__ X1, const float* __restrict__ X2,
    const float* __restrict__ W, float* __restrict__ out)
{
    const int b = blockIdx.z;
    X1 += (long)b * 256 * 1024;
    X2 += (long)b * 256 * 1024;
    const int bn = blockIdx.x * 128;

    __shared__ __align__(16) unsigned Ah[16 * 128], Al[16 * 128];
    __shared__ __align__(16) unsigned Bh[16 * 128], Bl[16 * 128];
    __shared__ float red[2][128];

    const int t = threadIdx.x, lane = t & 31, w = t >> 5;
    const int wm = w >> 2, wn = w & 3;

    float csum[4][2];
#pragma unroll
    for (int nf = 0; nf < 4; nf++) { csum[nf][0] = 0.f; csum[nf][1] = 0.f; }

    for (int mt = 0; mt < 256; mt += 128) {
        float acc[4][4][4];
#pragma unroll
        for (int i = 0; i < 4; i++)
#pragma unroll
            for (int j = 0; j < 4; j++)
#pragma unroll
                for (int q = 0; q < 4; q++) acc[i][j][q] = 0.f;

        for (int k0 = 0; k0 < 2048; k0 += 32) {
            const float* src = (k0 < 1024)
                ? X1 + (long)mt * 1024 + k0
                : X2 + (long)mt * 1024 + (k0 - 1024);
            load_trans(Ah, Al, src, 1024, t);
            load_direct(Bh, Bl, W + (long)k0 * 2048 + bn, 2048, t);
            __syncthreads();
            warp_compute(Ah, Al, Bh, Bl, acc, wm, wn, lane);
            __syncthreads();
        }
#pragma unroll
        for (int mf = 0; mf < 4; mf++)
#pragma unroll
            for (int nf = 0; nf < 4; nf++) {
                csum[nf][0] += tanhf(acc[mf][nf][0]) + tanhf(acc[mf][nf][2]);
                csum[nf][1] += tanhf(acc[mf][nf][1]) + tanhf(acc[mf][nf][3]);
            }
    }

    // reduce across the 8 row-groups (lanes sharing lane&3)
#pragma unroll
    for (int off = 4; off <= 16; off <<= 1)
#pragma unroll
        for (int nf = 0; nf < 4; nf++) {
            csum[nf][0] += __shfl_xor_sync(0xffffffffu, csum[nf][0], off);
            csum[nf][1] += __shfl_xor_sync(0xffffffffu, csum[nf][1], off);
        }
    if (lane < 4) {
#pragma unroll
        for (int nf = 0; nf < 4; nf++) {
            red[wm][wn * 32 + nf * 8 + 2 * lane + 0] = csum[nf][0];
            red[wm][wn * 32 + nf * 8 + 2 * lane + 1] = csum[nf][1];
        }
    }
    __syncthreads();
    if (t < 128) out[(long)b * 2048 + bn + t] = red[0][t] + red[1][t];
}

// ---------------------------------------------------------------------------
// Row softmax over 256 columns, in place. One warp per row.
// ---------------------------------------------------------------------------
__global__ void softmax256_kernel(float* __restrict__ E)
{
    const long row = (long)blockIdx.x * 8 + threadIdx.y;
    float* r = E + row * 256;
    const int lane = threadIdx.x;

    float v[8];
    float mx = -1e30f;
#pragma unroll
    for (int i = 0; i < 8; i++) {
        v[i] = r[i * 32 + lane];
        mx = fmaxf(mx, v[i]);
    }
#pragma unroll
    for (int o = 16; o; o >>= 1) mx = fmaxf(mx, __shfl_xor_sync(0xffffffffu, mx, o));
    float s = 0.f;
#pragma unroll
    for (int i = 0; i < 8; i++) {
        v[i] = expf(v[i] - mx);
        s += v[i];
    }
#pragma unroll
    for (int o = 16; o; o >>= 1) s += __shfl_xor_sync(0xffffffffu, s, o);
    const float inv = 1.0f / s;
#pragma unroll
    for (int i = 0; i < 8; i++) r[i * 32 + lane] = v[i] * inv;
}

// ---------------------------------------------------------------------------
// Skinny MLP layer: out[m,n] = act( concat(A1,A2)[m,:] @ W[:,n] + bias[n] )
// ---------------------------------------------------------------------------
__global__ __launch_bounds__(128) void mlp_layer_kernel(
    const float* __restrict__ A1, const float* __restrict__ A2, int ksplit,
    const float* __restrict__ W, const float* __restrict__ bias,
    float* __restrict__ out, int N, int K, int do_tanh)
{
    const int n = blockIdx.x * 128 + threadIdx.x;
    const int m0 = blockIdx.y * 8;

    __shared__ float As[8][129];
    float acc[8];
#pragma unroll
    for (int i = 0; i < 8; i++) acc[i] = 0.f;

    for (int k0 = 0; k0 < K; k0 += 128) {
#pragma unroll
        for (int i = 0; i < 8; i++) {
            const int k = k0 + threadIdx.x;
            As[i][threadIdx.x] = (k < ksplit)
                ? A1[(long)(m0 + i) * ksplit + k]
                : A2[(long)(m0 + i) * ksplit + (k - ksplit)];
        }
        __syncthreads();
        for (int kk = 0; kk < 128; kk++) {
            const float wv = W[(long)(k0 + kk) * N + n];
#pragma unroll
            for (int i = 0; i < 8; i++) acc[i] += As[i][kk] * wv;
        }
        __syncthreads();
    }
    const float bb = bias[n];
#pragma unroll
    for (int i = 0; i < 8; i++) {
        float r = acc[i] + bb;
        out[(long)(m0 + i) * N + n] = do_tanh ? tanhf(r) : r;
    }
}

__global__ void final_layer_kernel(
    const float* __restrict__ A, const float* __restrict__ W3,
    const float* __restrict__ b3, float* __restrict__ out)
{
    const int m = blockIdx.x / 3;
    const int n = blockIdx.x % 3;
    const int lane = threadIdx.x;
    float s = 0.f;
    for (int k = lane; k < 2048; k += 32)
        s += A[(long)m * 2048 + k] * W3[(long)k * 3 + n];
#pragma unroll
    for (int o = 16; o; o >>= 1) s += __shfl_xor_sync(0xffffffffu, s, o);
    if (lane == 0) out[m * 3 + n] = s + b3[n];
}

// ---------------------------------------------------------------------------
extern "C" void kernel_launch(void* const* d_in, const int* in_sizes, int n_in,
                              void* d_out, int out_size)
{
    const float* premises   = (const float*)d_in[0];
    const float* hypotheses = (const float*)d_in[1];
    const float* W_F = (const float*)d_in[2];
    const float* W_G = (const float*)d_in[3];
    const float* W1  = (const float*)d_in[4];
    const float* b1  = (const float*)d_in[5];
    const float* W2  = (const float*)d_in[6];
    const float* b2  = (const float*)d_in[7];
    const float* W3  = (const float*)d_in[8];
    const float* b3  = (const float*)d_in[9];
    float* out = (float*)d_out;

    float* scratch = nullptr;
    cudaGetSymbolAddress((void**)&scratch, g_scratch);

    float* Fp     = scratch + OFF_FP;
    float* Fh     = scratch + OFF_FH;
    float* attn   = scratch + OFF_ATTN;
    float* betas  = scratch + OFF_BETA;
    float* alphas = scratch + OFF_ALPHA;
    float* S1     = scratch + OFF_S1;
    float* S2     = scratch + OFF_S2;
    float* a1     = scratch + OFF_A1;
    float* a2     = scratch + OFF_A2;

    // 1,2) Fp = tanh(P @ W_F), Fh = tanh(H @ W_F): [8192,1024]x[1024,1024]
    {
        dim3 g(1024 / 128, 8192 / 128, 1);
        split_gemm<1, 0, 1><<<g, 256>>>(premises, W_F, Fp, 8192, 1024, 1024,
                                        1024, 1024, 0, 0, 0);
        split_gemm<1, 0, 1><<<g, 256>>>(hypotheses, W_F, Fh, 8192, 1024, 1024,
                                        1024, 1024, 0, 0, 0);
    }
    // 3) E[b] = Fp[b] @ Fh[b]^T   (B is [N][K] -> load_trans)
    {
        dim3 g(2, 2, 32);
        split_gemm<1, 1, 0><<<g, 256>>>(Fp, Fh, attn, 256, 256, 1024,
                                        1024, 1024, 256L * 1024, 256L * 1024, 256L * 256);
    }
    // 4) softmax rows
    softmax256_kernel<<<1024, dim3(32, 8)>>>(attn);
    // 5) betas[b] = attn[b] @ H[b]
    {
        dim3 g(8, 2, 32);
        split_gemm<1, 0, 0><<<g, 256>>>(attn, hypotheses, betas, 256, 1024, 256,
                                        256, 1024, 256L * 256, 256L * 1024, 256L * 1024);
        // 6) alphas[b] = attn[b]^T @ P[b]  (A gmem is [K][M] -> load_direct)
        split_gemm<0, 0, 0><<<g, 256>>>(attn, premises, alphas, 256, 1024, 256,
                                        256, 1024, 256L * 256, 256L * 1024, 256L * 1024);
    }
    // 7,8) compare (fused GEMM + tanh + sequence-sum)
    {
        dim3 g(2048 / 128, 1, 32);
        compare_split<<<g, 256>>>(premises, betas, W_G, S1);
        compare_split<<<g, 256>>>(hypotheses, alphas, W_G, S2);
    }
    // 9,10) classifier
    mlp_layer_kernel<<<dim3(2048 / 128, 4), 128>>>(S1, S2, 2048, W1, b1, a1, 2048, 4096, 1);
    mlp_layer_kernel<<<dim3(2048 / 128, 4), 128>>>(a1, a1, 2048, W2, b2, a2, 2048, 2048, 1);
    // 11) logits
    final_layer_kernel<<<96, 32>>>(a2, W3, b3, out);
}

// round 5
// speedup vs baseline: 1.5843x; 1.0208x over previous
#include <cuda_runtime.h>
#include <math.h>

// ---------------------------------------------------------------------------
// Decomposable-Attention NLI forward. All large GEMMs on bf16 tensor cores
// with hi/lo split (4 products: AhBh+AhBl+AlBh+AlBl, fp32 accum ~ fp32 exact).
// Operands pre-packed in gmem as u32 words = (bf16 even-k | bf16 odd-k << 16)
// in "direct" layout [kp][col], so GEMM loads are pure cp.async 16B copies.
// B=32, L=256, D=1024, FF=2048.
// ---------------------------------------------------------------------------

// ---- scratch offsets (u32 words) ----
#define OFF_PKT_H 0L
#define OFF_PKT_L 4194304L
#define OFF_HKT_H 8388608L
#define OFF_HKT_L 12582912L
#define OFF_FPT_H 16777216L
#define OFF_FPT_L 20971520L
#define OFF_FHT_H 25165824L
#define OFF_FHT_L 29360128L
#define OFF_PPT_H 33554432L
#define OFF_PPT_L 37748736L
#define OFF_HPT_H 41943040L
#define OFF_HPT_L 46137344L
#define OFF_BET_H 50331648L
#define OFF_BET_L 54525952L
#define OFF_ALP_H 58720256L
#define OFF_ALP_L 62914560L
#define OFF_WFT_H 67108864L
#define OFF_WFT_L 67633152L
#define OFF_WGT_H 68157440L
#define OFF_WGT_L 70254592L
#define OFF_ATP_H 72351744L
#define OFF_ATP_L 73400320L
#define OFF_ATH_H 74448896L
#define OFF_ATH_L 75497472L
#define OFF_E     76546048L
#define OFF_S1    78643200L
#define OFF_S2    78708736L
#define OFF_A1    78774272L
#define OFF_A2    78839808L
#define SCRATCH_WORDS 78905344L

__device__ __align__(1024) unsigned g_scratch[SCRATCH_WORDS];

// Split two k-consecutive floats into packed bf16x2 hi and lo words.
// low 16 bits = even k, high 16 bits = odd k (mma frag order).
__device__ __forceinline__ void split2(float v0, float v1, unsigned& hi, unsigned& lo) {
    unsigned h;
    asm("cvt.rn.bf16x2.f32 %0, %1, %2;" : "=r"(h) : "f"(v1), "f"(v0));
    float h0 = __uint_as_float(h << 16);
    float h1 = __uint_as_float(h & 0xFFFF0000u);
    float r0 = v0 - h0;
    float r1 = v1 - h1;
    asm("cvt.rn.bf16x2.f32 %0, %1, %2;" : "=r"(lo) : "f"(r1), "f"(r0));
    hi = h;
}

// Swizzled smem word layout: 16(kp) x 128(col) words. Proven conflict-free.
__device__ __forceinline__ int swz(int kp, int m) {
    return (kp << 7) + (m ^ ((8 * (kp & 3)) ^ (4 * ((kp >> 2) & 7))));
}

__device__ __forceinline__ void mma_bf16(float* c, const unsigned* a, const unsigned* b) {
    asm volatile(
        "mma.sync.aligned.m16n8k16.row.col.f32.bf16.bf16.f32 "
        "{%0,%1,%2,%3},{%4,%5,%6,%7},{%8,%9},{%0,%1,%2,%3};\n"
        : "+f"(c[0]), "+f"(c[1]), "+f"(c[2]), "+f"(c[3])
        : "r"(a[0]), "r"(a[1]), "r"(a[2]), "r"(a[3]), "r"(b[0]), "r"(b[1]));
}

// cp.async one 16-kp x 128-col tile from direct-layout gmem (row stride ldw words)
__device__ __forceinline__ void ld_tile(unsigned* S, const unsigned* G, long ldw, int t) {
#pragma unroll
    for (int i = 0; i < 2; i++) {
        const int kp = (t >> 5) + (i << 3);
        const int n4 = (t & 31) << 2;
        const int gk = (8 * (kp & 3)) ^ (4 * ((kp >> 2) & 7));
        unsigned dst = (unsigned)__cvta_generic_to_shared(S + (kp << 7) + (n4 ^ gk));
        asm volatile("cp.async.cg.shared.global [%0], [%1], 16;"
                     :: "r"(dst), "l"(G + (long)kp * ldw + n4) : "memory");
    }
}

// per-warp compute over a staged 32-deep K tile. Stage layout:
// [0]=Ah [2048]=Al [4096]=Bh [6144]=Bl. 4 products per frag.
__device__ __forceinline__ void warp_compute(const unsigned* S, float acc[4][4][4],
                                             int wm, int wn, int lane) {
    const unsigned* Ah = S;
    const unsigned* Al = S + 2048;
    const unsigned* Bh = S + 4096;
    const unsigned* Bl = S + 6144;
    const int c = lane & 3, r = lane >> 2;
#pragma unroll
    for (int s = 0; s < 2; s++) {
        const int kpa = 8 * s + c, kpb = kpa + 4;
        unsigned bh[4][2], bl[4][2];
#pragma unroll
        for (int nf = 0; nf < 4; nf++) {
            const int n = wn * 32 + nf * 8 + r;
            bh[nf][0] = Bh[swz(kpa, n)]; bh[nf][1] = Bh[swz(kpb, n)];
            bl[nf][0] = Bl[swz(kpa, n)]; bl[nf][1] = Bl[swz(kpb, n)];
        }
#pragma unroll
        for (int mf = 0; mf < 4; mf++) {
            const int m = wm * 64 + mf * 16 + r;
            unsigned ah[4], al[4];
            ah[0] = Ah[swz(kpa, m)]; ah[1] = Ah[swz(kpa, m + 8)];
            ah[2] = Ah[swz(kpb, m)]; ah[3] = Ah[swz(kpb, m + 8)];
            al[0] = Al[swz(kpa, m)]; al[1] = Al[swz(kpa, m + 8)];
            al[2] = Al[swz(kpb, m)]; al[3] = Al[swz(kpb, m + 8)];
#pragma unroll
            for (int nf = 0; nf < 4; nf++) {
                mma_bf16(acc[mf][nf], ah, bh[nf]);
                mma_bf16(acc[mf][nf], ah, bl[nf]);
                mma_bf16(acc[mf][nf], al, bh[nf]);
                mma_bf16(acc[mf][nf], al, bl[nf]);
            }
        }
    }
}

// ---------------------------------------------------------------------------
// pack_kT: fp32 [Mdim][Kd] (k contiguous) -> direct layout [Kd/2][Mdim] h/l.
// ---------------------------------------------------------------------------
__global__ __launch_bounds__(256) void pack_kT_kernel(
    const float* __restrict__ X, unsigned* __restrict__ H, unsigned* __restrict__ L,
    int Mdim, int Kd)
{
    __shared__ unsigned sh[32][68];
    __shared__ unsigned sl[32][68];
    const int kp0 = blockIdx.x * 32, m0 = blockIdx.y * 64;
    const int t = threadIdx.x;
#pragma unroll
    for (int i = 0; i < 8; i++) {
        const int m_l = (t >> 5) + (i << 3);
        const int kpl = t & 31;
        float2 v = *(const float2*)&X[(long)(m0 + m_l) * Kd + 2 * (kp0 + kpl)];
        unsigned h, l;
        split2(v.x, v.y, h, l);
        sh[kpl][m_l] = h; sl[kpl][m_l] = l;
    }
    __syncthreads();
#pragma unroll
    for (int i = 0; i < 2; i++) {
        const int kpl = (t >> 4) + (i << 4);
        const int m4 = (t & 15) << 2;
        const long o = (long)(kp0 + kpl) * Mdim + m0 + m4;
        *(uint4*)&H[o] = *(uint4*)&sh[kpl][m4];
        *(uint4*)&L[o] = *(uint4*)&sl[kpl][m4];
    }
}

// ---------------------------------------------------------------------------
// pack_rows: fp32 [R][cols] -> [R/2][cols] h/l, word = pack(row 2r, row 2r+1).
// ---------------------------------------------------------------------------
__global__ __launch_bounds__(256) void pack_rows_kernel(
    const float* __restrict__ X, unsigned* __restrict__ H, unsigned* __restrict__ L,
    int cols, long nw4)
{
    const long w4 = (long)blockIdx.x * 256 + threadIdx.x;
    if (w4 >= nw4) return;
    const int c4pr = cols >> 2;
    const long r = w4 / c4pr;
    const int c = (int)(w4 % c4pr) << 2;
    const float* r0 = X + 2 * r * (long)cols + c;
    float4 a = *(const float4*)r0;
    float4 b = *(const float4*)(r0 + cols);
    unsigned h[4], l[4];
    split2(a.x, b.x, h[0], l[0]);
    split2(a.y, b.y, h[1], l[1]);
    split2(a.z, b.z, h[2], l[2]);
    split2(a.w, b.w, h[3], l[3]);
    const long o = r * (long)cols + c;
    *(uint4*)&H[o] = make_uint4(h[0], h[1], h[2], h[3]);
    *(uint4*)&L[o] = make_uint4(l[0], l[1], l[2], l[3]);
}

// ---------------------------------------------------------------------------
// Generic packed-bf16 GEMM, 128x128 tile, 3-stage cp.async pipeline.
// EPI: 0 = fp32 store to C; 1 = packed-T store; 2 = tanh + packed-T store.
// Operands are direct-layout [kp][col] u32 arrays (h + l).
// ---------------------------------------------------------------------------
template <int EPI>
__global__ __launch_bounds__(256, 2) void gemm_q(
    const unsigned* __restrict__ Ah, const unsigned* __restrict__ Al, long lda, long sA,
    const unsigned* __restrict__ Bh, const unsigned* __restrict__ Bl, long ldb, long sB,
    float* __restrict__ C, long ldc, long sC,
    unsigned* __restrict__ CTh, unsigned* __restrict__ CTl, long ldct, long sCT,
    int K)
{
    extern __shared__ unsigned smp[];
    const int t = threadIdx.x, lane = t & 31, w = t >> 5;
    const int wm = w >> 2, wn = w & 3;
    const int bm = blockIdx.y * 128, bn = blockIdx.x * 128;
    const int z = blockIdx.z;
    const unsigned* Abh = Ah + z * sA + bm;
    const unsigned* Abl = Al + z * sA + bm;
    const unsigned* Bbh = Bh + z * sB + bn;
    const unsigned* Bbl = Bl + z * sB + bn;
    const int nk = K >> 5;

    float acc[4][4][4];
#pragma unroll
    for (int i = 0; i < 4; i++)
#pragma unroll
        for (int j = 0; j < 4; j++)
#pragma unroll
            for (int q = 0; q < 4; q++) acc[i][j][q] = 0.f;

    auto issue = [&](int j, int s) {
        unsigned* st = smp + s * 8192;
        const long ro = (long)(j * 16);
        ld_tile(st,        Abh + ro * lda, lda, t);
        ld_tile(st + 2048, Abl + ro * lda, lda, t);
        ld_tile(st + 4096, Bbh + ro * ldb, ldb, t);
        ld_tile(st + 6144, Bbl + ro * ldb, ldb, t);
        asm volatile("cp.async.commit_group;" ::: "memory");
    };

    issue(0, 0);
    if (nk > 1) issue(1, 1);
    for (int j = 0; j < nk; j++) {
        if (j + 2 < nk) issue(j + 2, (j + 2) % 3);
        if (j + 2 < nk)      asm volatile("cp.async.wait_group 2;" ::: "memory");
        else if (j + 1 < nk) asm volatile("cp.async.wait_group 1;" ::: "memory");
        else                 asm volatile("cp.async.wait_group 0;" ::: "memory");
        __syncthreads();
        warp_compute(smp + (j % 3) * 8192, acc, wm, wn, lane);
        __syncthreads();
    }

    const int r = lane >> 2, c2 = (lane & 3) * 2;
#pragma unroll
    for (int mf = 0; mf < 4; mf++)
#pragma unroll
        for (int nf = 0; nf < 4; nf++) {
            const int row = bm + wm * 64 + mf * 16 + r;
            const int col = bn + wn * 32 + nf * 8 + c2;
            float v0 = acc[mf][nf][0], v1 = acc[mf][nf][1];
            float v2 = acc[mf][nf][2], v3 = acc[mf][nf][3];
            if (EPI == 2) {
                v0 = tanhf(v0); v1 = tanhf(v1); v2 = tanhf(v2); v3 = tanhf(v3);
            }
            if (EPI == 0) {
                *(float2*)&C[z * sC + (long)row * ldc + col] = make_float2(v0, v1);
                *(float2*)&C[z * sC + (long)(row + 8) * ldc + col] = make_float2(v2, v3);
            } else {
                unsigned h0, l0, h1, l1;
                split2(v0, v1, h0, l0);
                split2(v2, v3, h1, l1);
                const long o = z * sCT + (long)(col >> 1) * ldct;
                CTh[o + row] = h0;     CTl[o + row] = l0;
                CTh[o + row + 8] = h1; CTl[o + row + 8] = l1;
            }
        }
}

// ---------------------------------------------------------------------------
// Softmax over 256 cols + write both packed attn layouts:
//  attn_pT[b][pp][h] = pack over p pairs (for alphas-A)
//  attn_hT[b][hp][p] = pack over h pairs (for betas-A)
// ---------------------------------------------------------------------------
__global__ void softmax_pack_kernel(
    const float* __restrict__ E,
    unsigned* __restrict__ APh, unsigned* __restrict__ APl,
    unsigned* __restrict__ AHh, unsigned* __restrict__ AHl)
{
    __shared__ float smr[8][258];
    const int b = blockIdx.x >> 5;
    const int p0 = (blockIdx.x & 31) << 3;
    const int lane = threadIdx.x, ty = threadIdx.y;
    const float* row = E + ((long)b * 256 + p0 + ty) * 256;

    float v[8];
    float mx = -1e30f;
#pragma unroll
    for (int i = 0; i < 8; i++) {
        v[i] = row[i * 32 + lane];
        mx = fmaxf(mx, v[i]);
    }
#pragma unroll
    for (int o = 16; o; o >>= 1) mx = fmaxf(mx, __shfl_xor_sync(0xffffffffu, mx, o));
    float s = 0.f;
#pragma unroll
    for (int i = 0; i < 8; i++) { v[i] = expf(v[i] - mx); s += v[i]; }
#pragma unroll
    for (int o = 16; o; o >>= 1) s += __shfl_xor_sync(0xffffffffu, s, o);
    const float inv = 1.0f / s;
#pragma unroll
    for (int i = 0; i < 8; i++) smr[ty][i * 32 + lane] = v[i] * inv;
    __syncthreads();

    const int t = ty * 32 + lane;
    {   // attn_pT: pack rows (2ppl, 2ppl+1), h contiguous
        const int ppl = t >> 6;
        const int h4 = (t & 63) << 2;
        unsigned h[4], l[4];
#pragma unroll
        for (int q = 0; q < 4; q++)
            split2(smr[2 * ppl][h4 + q], smr[2 * ppl + 1][h4 + q], h[q], l[q]);
        const long o = (long)b * 32768 + (long)((p0 >> 1) + ppl) * 256 + h4;
        *(uint4*)&APh[o] = make_uint4(h[0], h[1], h[2], h[3]);
        *(uint4*)&APl[o] = make_uint4(l[0], l[1], l[2], l[3]);
    }
#pragma unroll
    for (int i = 0; i < 4; i++) {  // attn_hT: pack cols (2hp, 2hp+1) at row p
        const int hp = (t >> 3) + (i << 5);
        const int pl = t & 7;
        unsigned hh, ll;
        split2(smr[pl][2 * hp], smr[pl][2 * hp + 1], hh, ll);
        AHh[(long)b * 32768 + (long)hp * 256 + p0 + pl] = hh;
        AHl[(long)b * 32768 + (long)hp * 256 + p0 + pl] = ll;
    }
}

// ---------------------------------------------------------------------------
// Fused compare: out[b,n] = sum_{p<256} tanh( concat(X1,X2)[b,p,:] @ W[:,n] )
// X1 = PkT/HkT slice (lda 8192, col off b*256), X2 = betasT/alphasT (per-batch
// [512][256]), W = WGT [1024][2048]. 3-stage cp.async pipeline.
// ---------------------------------------------------------------------------
__global__ __launch_bounds__(256, 2) void compare_q(
    const unsigned* __restrict__ X1h, const unsigned* __restrict__ X1l,
    const unsigned* __restrict__ X2h, const unsigned* __restrict__ X2l,
    const unsigned* __restrict__ Wh, const unsigned* __restrict__ Wl,
    float* __restrict__ out)
{
    extern __shared__ unsigned smp[];
    const int t = threadIdx.x, lane = t & 31, w = t >> 5;
    const int wm = w >> 2, wn = w & 3;
    const int z = blockIdx.z;
    const int bn = blockIdx.x * 128;
    const unsigned* Wbh = Wh + bn;
    const unsigned* Wbl = Wl + bn;
    const int nk = 64;

    float csum[4][2];
#pragma unroll
    for (int nf = 0; nf < 4; nf++) { csum[nf][0] = 0.f; csum[nf][1] = 0.f; }

    for (int mt = 0; mt < 256; mt += 128) {
        float acc[4][4][4];
#pragma unroll
        for (int i = 0; i < 4; i++)
#pragma unroll
            for (int j = 0; j < 4; j++)
#pragma unroll
                for (int q = 0; q < 4; q++) acc[i][j][q] = 0.f;

        auto issue = [&](int j, int s) {
            unsigned* st = smp + s * 8192;
            if (j < 32) {
                const long ro = (long)(j * 16) * 8192 + z * 256 + mt;
                ld_tile(st,        X1h + ro, 8192, t);
                ld_tile(st + 2048, X1l + ro, 8192, t);
            } else {
                const long ro = (long)z * 131072 + (long)((j - 32) * 16) * 256 + mt;
                ld_tile(st,        X2h + ro, 256, t);
                ld_tile(st + 2048, X2l + ro, 256, t);
            }
            const long wo = (long)(j * 16) * 2048;
            ld_tile(st + 4096, Wbh + wo, 2048, t);
            ld_tile(st + 6144, Wbl + wo, 2048, t);
            asm volatile("cp.async.commit_group;" ::: "memory");
        };

        issue(0, 0);
        issue(1, 1);
        for (int j = 0; j < nk; j++) {
            if (j + 2 < nk) issue(j + 2, (j + 2) % 3);
            if (j + 2 < nk)      asm volatile("cp.async.wait_group 2;" ::: "memory");
            else if (j + 1 < nk) asm volatile("cp.async.wait_group 1;" ::: "memory");
            else                 asm volatile("cp.async.wait_group 0;" ::: "memory");
            __syncthreads();
            warp_compute(smp + (j % 3) * 8192, acc, wm, wn, lane);
            __syncthreads();
        }
#pragma unroll
        for (int mf = 0; mf < 4; mf++)
#pragma unroll
            for (int nf = 0; nf < 4; nf++) {
                csum[nf][0] += tanhf(acc[mf][nf][0]) + tanhf(acc[mf][nf][2]);
                csum[nf][1] += tanhf(acc[mf][nf][1]) + tanhf(acc[mf][nf][3]);
            }
    }

#pragma unroll
    for (int off = 4; off <= 16; off <<= 1)
#pragma unroll
        for (int nf = 0; nf < 4; nf++) {
            csum[nf][0] += __shfl_xor_sync(0xffffffffu, csum[nf][0], off);
            csum[nf][1] += __shfl_xor_sync(0xffffffffu, csum[nf][1], off);
        }
    float* red = (float*)smp;  // pipeline fully drained; reuse stage memory
    if (lane < 4) {
#pragma unroll
        for (int nf = 0; nf < 4; nf++) {
            red[wm * 128 + wn * 32 + nf * 8 + 2 * lane + 0] = csum[nf][0];
            red[wm * 128 + wn * 32 + nf * 8 + 2 * lane + 1] = csum[nf][1];
        }
    }
    __syncthreads();
    if (t < 128) out[(long)z * 2048 + bn + t] = red[t] + red[128 + t];
}

// ---------------------------------------------------------------------------
// Skinny classifier MLP + final layer (fp32; negligible time).
// ---------------------------------------------------------------------------
__global__ __launch_bounds__(128) void mlp_layer_kernel(
    const float* __restrict__ A1, const float* __restrict__ A2, int ksplit,
    const float* __restrict__ W, const float* __restrict__ bias,
    float* __restrict__ out, int N, int K, int do_tanh)
{
    const int n = blockIdx.x * 128 + threadIdx.x;
    const int m0 = blockIdx.y * 8;

    __shared__ float As[8][129];
    float acc[8];
#pragma unroll
    for (int i = 0; i < 8; i++) acc[i] = 0.f;

    for (int k0 = 0; k0 < K; k0 += 128) {
#pragma unroll
        for (int i = 0; i < 8; i++) {
            const int k = k0 + threadIdx.x;
            As[i][threadIdx.x] = (k < ksplit)
                ? A1[(long)(m0 + i) * ksplit + k]
                : A2[(long)(m0 + i) * ksplit + (k - ksplit)];
        }
        __syncthreads();
        for (int kk = 0; kk < 128; kk++) {
            const float wv = W[(long)(k0 + kk) * N + n];
#pragma unroll
            for (int i = 0; i < 8; i++) acc[i] += As[i][kk] * wv;
        }
        __syncthreads();
    }
    const float bb = bias[n];
#pragma unroll
    for (int i = 0; i < 8; i++) {
        float r = acc[i] + bb;
        out[(long)(m0 + i) * N + n] = do_tanh ? tanhf(r) : r;
    }
}

__global__ void final_layer_kernel(
    const float* __restrict__ A, const float* __restrict__ W3,
    const float* __restrict__ b3, float* __restrict__ out)
{
    const int m = blockIdx.x / 3;
    const int n = blockIdx.x % 3;
    const int lane = threadIdx.x;
    float s = 0.f;
    for (int k = lane; k < 2048; k += 32)
        s += A[(long)m * 2048 + k] * W3[(long)k * 3 + n];
#pragma unroll
    for (int o = 16; o; o >>= 1) s += __shfl_xor_sync(0xffffffffu, s, o);
    if (lane == 0) out[m * 3 + n] = s + b3[n];
}

// ---------------------------------------------------------------------------
extern "C" void kernel_launch(void* const* d_in, const int* in_sizes, int n_in,
                              void* d_out, int out_size)
{
    const float* premises   = (const float*)d_in[0];
    const float* hypotheses = (const float*)d_in[1];
    const float* W_F = (const float*)d_in[2];
    const float* W_G = (const float*)d_in[3];
    const float* W1  = (const float*)d_in[4];
    const float* b1  = (const float*)d_in[5];
    const float* W2  = (const float*)d_in[6];
    const float* b2  = (const float*)d_in[7];
    const float* W3  = (const float*)d_in[8];
    const float* b3  = (const float*)d_in[9];
    float* out = (float*)d_out;

    unsigned* sc = nullptr;
    cudaGetSymbolAddress((void**)&sc, g_scratch);

    const int SMEM = 3 * 8192 * 4;  // 96KB
    cudaFuncSetAttribute(gemm_q<0>, cudaFuncAttributeMaxDynamicSharedMemorySize, SMEM);
    cudaFuncSetAttribute(gemm_q<1>, cudaFuncAttributeMaxDynamicSharedMemorySize, SMEM);
    cudaFuncSetAttribute(gemm_q<2>, cudaFuncAttributeMaxDynamicSharedMemorySize, SMEM);
    cudaFuncSetAttribute(compare_q, cudaFuncAttributeMaxDynamicSharedMemorySize, SMEM);

    float* E  = (float*)(sc + OFF_E);
    float* S1 = (float*)(sc + OFF_S1);
    float* S2 = (float*)(sc + OFF_S2);
    float* a1 = (float*)(sc + OFF_A1);
    float* a2 = (float*)(sc + OFF_A2);

    // ---- pack inputs ----
    pack_kT_kernel<<<dim3(16, 128), 256>>>(premises,   sc + OFF_PKT_H, sc + OFF_PKT_L, 8192, 1024);
    pack_kT_kernel<<<dim3(16, 128), 256>>>(hypotheses, sc + OFF_HKT_H, sc + OFF_HKT_L, 8192, 1024);
    pack_rows_kernel<<<512,  256>>>(W_F, sc + OFF_WFT_H, sc + OFF_WFT_L, 1024, 131072);
    pack_rows_kernel<<<2048, 256>>>(W_G, sc + OFF_WGT_H, sc + OFF_WGT_L, 2048, 524288);
    pack_rows_kernel<<<4096, 256>>>(premises,   sc + OFF_PPT_H, sc + OFF_PPT_L, 1024, 1048576);
    pack_rows_kernel<<<4096, 256>>>(hypotheses, sc + OFF_HPT_H, sc + OFF_HPT_L, 1024, 1048576);

    // ---- projections: Fp/Fh = tanh(X @ W_F), packed-T output ----
    gemm_q<2><<<dim3(8, 64, 1), 256, SMEM>>>(
        sc + OFF_PKT_H, sc + OFF_PKT_L, 8192, 0,
        sc + OFF_WFT_H, sc + OFF_WFT_L, 1024, 0,
        nullptr, 0, 0, sc + OFF_FPT_H, sc + OFF_FPT_L, 8192, 0, 1024);
    gemm_q<2><<<dim3(8, 64, 1), 256, SMEM>>>(
        sc + OFF_HKT_H, sc + OFF_HKT_L, 8192, 0,
        sc + OFF_WFT_H, sc + OFF_WFT_L, 1024, 0,
        nullptr, 0, 0, sc + OFF_FHT_H, sc + OFF_FHT_L, 8192, 0, 1024);

    // ---- E[b] = Fp[b] @ Fh[b]^T (fp32 out) ----
    gemm_q<0><<<dim3(2, 2, 32), 256, SMEM>>>(
        sc + OFF_FPT_H, sc + OFF_FPT_L, 8192, 256,
        sc + OFF_FHT_H, sc + OFF_FHT_L, 8192, 256,
        E, 256, 65536, nullptr, nullptr, 0, 0, 1024);

    // ---- softmax + pack both attn layouts ----
    softmax_pack_kernel<<<1024, dim3(32, 8)>>>(
        E, sc + OFF_ATP_H, sc + OFF_ATP_L, sc + OFF_ATH_H, sc + OFF_ATH_L);

    // ---- betas = attn @ H ; alphas = attn^T @ P (packed-T out) ----
    gemm_q<1><<<dim3(8, 2, 32), 256, SMEM>>>(
        sc + OFF_ATH_H, sc + OFF_ATH_L, 256, 32768,
        sc + OFF_HPT_H, sc + OFF_HPT_L, 1024, 131072,
        nullptr, 0, 0, sc + OFF_BET_H, sc + OFF_BET_L, 256, 131072, 256);
    gemm_q<1><<<dim3(8, 2, 32), 256, SMEM>>>(
        sc + OFF_ATP_H, sc + OFF_ATP_L, 256, 32768,
        sc + OFF_PPT_H, sc + OFF_PPT_L, 1024, 131072,
        nullptr, 0, 0, sc + OFF_ALP_H, sc + OFF_ALP_L, 256, 131072, 256);

    // ---- compare (fused GEMM + tanh + sequence-sum) ----
    compare_q<<<dim3(16, 1, 32), 256, SMEM>>>(
        sc + OFF_PKT_H, sc + OFF_PKT_L, sc + OFF_BET_H, sc + OFF_BET_L,
        sc + OFF_WGT_H, sc + OFF_WGT_L, S1);
    compare_q<<<dim3(16, 1, 32), 256, SMEM>>>(
        sc + OFF_HKT_H, sc + OFF_HKT_L, sc + OFF_ALP_H, sc + OFF_ALP_L,
        sc + OFF_WGT_H, sc + OFF_WGT_L, S2);

    // ---- classifier ----
    mlp_layer_kernel<<<dim3(16, 4), 128>>>(S1, S2, 2048, W1, b1, a1, 2048, 4096, 1);
    mlp_layer_kernel<<<dim3(16, 4), 128>>>(a1, a1, 2048, W2, b2, a2, 2048, 2048, 1);
    final_layer_kernel<<<96, 32>>>(a2, W3, b3, out);
}

// round 6
// speedup vs baseline: 1.5866x; 1.0015x over previous
#include <cuda_runtime.h>
#include <math.h>

// ---------------------------------------------------------------------------
// Decomposable-Attention NLI forward. All large GEMMs on bf16 tensor cores
// with hi/lo split (4 products: AhBh+AhBl+AlBh+AlBl, fp32 accum ~ fp32 exact).
// Operands pre-packed in gmem as u32 words = (bf16 even-k | bf16 odd-k << 16)
// in "direct" layout [kp][col], so GEMM loads are pure cp.async 16B copies.
// B=32, L=256, D=1024, FF=2048.
// ---------------------------------------------------------------------------

// ---- scratch offsets (u32 words) ----
#define OFF_PKT_H 0L
#define OFF_PKT_L 4194304L
#define OFF_HKT_H 8388608L
#define OFF_HKT_L 12582912L
#define OFF_FPT_H 16777216L
#define OFF_FPT_L 20971520L
#define OFF_FHT_H 25165824L
#define OFF_FHT_L 29360128L
#define OFF_PPT_H 33554432L
#define OFF_PPT_L 37748736L
#define OFF_HPT_H 41943040L
#define OFF_HPT_L 46137344L
#define OFF_BET_H 50331648L
#define OFF_BET_L 54525952L
#define OFF_ALP_H 58720256L
#define OFF_ALP_L 62914560L
#define OFF_WFT_H 67108864L
#define OFF_WFT_L 67633152L
#define OFF_WGT_H 68157440L
#define OFF_WGT_L 70254592L
#define OFF_ATP_H 72351744L
#define OFF_ATP_L 73400320L
#define OFF_ATH_H 74448896L
#define OFF_ATH_L 75497472L
#define OFF_E     76546048L
#define OFF_S1    78643200L
#define OFF_S2    78708736L
#define OFF_A1    78774272L
#define OFF_A2    78839808L
#define SCRATCH_WORDS 78905344L

__device__ __align__(1024) unsigned g_scratch[SCRATCH_WORDS];

// Split two k-consecutive floats into packed bf16x2 hi and lo words.
// low 16 bits = even k, high 16 bits = odd k (mma frag order).
__device__ __forceinline__ void split2(float v0, float v1, unsigned& hi, unsigned& lo) {
    unsigned h;
    asm("cvt.rn.bf16x2.f32 %0, %1, %2;" : "=r"(h) : "f"(v1), "f"(v0));
    float h0 = __uint_as_float(h << 16);
    float h1 = __uint_as_float(h & 0xFFFF0000u);
    float r0 = v0 - h0;
    float r1 = v1 - h1;
    asm("cvt.rn.bf16x2.f32 %0, %1, %2;" : "=r"(lo) : "f"(r1), "f"(r0));
    hi = h;
}

// Swizzled smem word layout: 16(kp) x 128(col) words. Proven conflict-free.
__device__ __forceinline__ int swz(int kp, int m) {
    return (kp << 7) + (m ^ ((8 * (kp & 3)) ^ (4 * ((kp >> 2) & 7))));
}

__device__ __forceinline__ void mma_bf16(float* c, const unsigned* a, const unsigned* b) {
    asm volatile(
        "mma.sync.aligned.m16n8k16.row.col.f32.bf16.bf16.f32 "
        "{%0,%1,%2,%3},{%4,%5,%6,%7},{%8,%9},{%0,%1,%2,%3};\n"
        : "+f"(c[0]), "+f"(c[1]), "+f"(c[2]), "+f"(c[3])
        : "r"(a[0]), "r"(a[1]), "r"(a[2]), "r"(a[3]), "r"(b[0]), "r"(b[1]));
}

// cp.async one 16-kp x 128-col tile from direct-layout gmem (row stride ldw words)
__device__ __forceinline__ void ld_tile(unsigned* S, const unsigned* G, long ldw, int t) {
#pragma unroll
    for (int i = 0; i < 2; i++) {
        const int kp = (t >> 5) + (i << 3);
        const int n4 = (t & 31) << 2;
        const int gk = (8 * (kp & 3)) ^ (4 * ((kp >> 2) & 7));
        unsigned dst = (unsigned)__cvta_generic_to_shared(S + (kp << 7) + (n4 ^ gk));
        asm volatile("cp.async.cg.shared.global [%0], [%1], 16;"
                     :: "r"(dst), "l"(G + (long)kp * ldw + n4) : "memory");
    }
}

// per-warp compute over a staged 32-deep K tile. Stage layout:
// [0]=Ah [2048]=Al [4096]=Bh [6144]=Bl. 4 products per frag.
__device__ __forceinline__ void warp_compute(const unsigned* S, float acc[4][4][4],
                                             int wm, int wn, int lane) {
    const unsigned* Ah = S;
    const unsigned* Al = S + 2048;
    const unsigned* Bh = S + 4096;
    const unsigned* Bl = S + 6144;
    const int c = lane & 3, r = lane >> 2;
#pragma unroll
    for (int s = 0; s < 2; s++) {
        const int kpa = 8 * s + c, kpb = kpa + 4;
        unsigned bh[4][2], bl[4][2];
#pragma unroll
        for (int nf = 0; nf < 4; nf++) {
            const int n = wn * 32 + nf * 8 + r;
            bh[nf][0] = Bh[swz(kpa, n)]; bh[nf][1] = Bh[swz(kpb, n)];
            bl[nf][0] = Bl[swz(kpa, n)]; bl[nf][1] = Bl[swz(kpb, n)];
        }
#pragma unroll
        for (int mf = 0; mf < 4; mf++) {
            const int m = wm * 64 + mf * 16 + r;
            unsigned ah[4], al[4];
            ah[0] = Ah[swz(kpa, m)]; ah[1] = Ah[swz(kpa, m + 8)];
            ah[2] = Ah[swz(kpb, m)]; ah[3] = Ah[swz(kpb, m + 8)];
            al[0] = Al[swz(kpa, m)]; al[1] = Al[swz(kpa, m + 8)];
            al[2] = Al[swz(kpb, m)]; al[3] = Al[swz(kpb, m + 8)];
#pragma unroll
            for (int nf = 0; nf < 4; nf++) {
                mma_bf16(acc[mf][nf], ah, bh[nf]);
                mma_bf16(acc[mf][nf], ah, bl[nf]);
                mma_bf16(acc[mf][nf], al, bh[nf]);
                mma_bf16(acc[mf][nf], al, bl[nf]);
            }
        }
    }
}

// ---------------------------------------------------------------------------
// pack_kT: fp32 [Mdim][Kd] (k contiguous) -> direct layout [Kd/2][Mdim] h/l.
// ---------------------------------------------------------------------------
__global__ __launch_bounds__(256) void pack_kT_kernel(
    const float* __restrict__ X, unsigned* __restrict__ H, unsigned* __restrict__ L,
    int Mdim, int Kd)
{
    __shared__ unsigned sh[32][68];
    __shared__ unsigned sl[32][68];
    const int kp0 = blockIdx.x * 32, m0 = blockIdx.y * 64;
    const int t = threadIdx.x;
#pragma unroll
    for (int i = 0; i < 8; i++) {
        const int m_l = (t >> 5) + (i << 3);
        const int kpl = t & 31;
        float2 v = *(const float2*)&X[(long)(m0 + m_l) * Kd + 2 * (kp0 + kpl)];
        unsigned h, l;
        split2(v.x, v.y, h, l);
        sh[kpl][m_l] = h; sl[kpl][m_l] = l;
    }
    __syncthreads();
#pragma unroll
    for (int i = 0; i < 2; i++) {
        const int kpl = (t >> 4) + (i << 4);
        const int m4 = (t & 15) << 2;
        const long o = (long)(kp0 + kpl) * Mdim + m0 + m4;
        *(uint4*)&H[o] = *(uint4*)&sh[kpl][m4];
        *(uint4*)&L[o] = *(uint4*)&sl[kpl][m4];
    }
}

// ---------------------------------------------------------------------------
// pack_rows: fp32 [R][cols] -> [R/2][cols] h/l, word = pack(row 2r, row 2r+1).
// ---------------------------------------------------------------------------
__global__ __launch_bounds__(256) void pack_rows_kernel(
    const float* __restrict__ X, unsigned* __restrict__ H, unsigned* __restrict__ L,
    int cols, long nw4)
{
    const long w4 = (long)blockIdx.x * 256 + threadIdx.x;
    if (w4 >= nw4) return;
    const int c4pr = cols >> 2;
    const long r = w4 / c4pr;
    const int c = (int)(w4 % c4pr) << 2;
    const float* r0 = X + 2 * r * (long)cols + c;
    float4 a = *(const float4*)r0;
    float4 b = *(const float4*)(r0 + cols);
    unsigned h[4], l[4];
    split2(a.x, b.x, h[0], l[0]);
    split2(a.y, b.y, h[1], l[1]);
    split2(a.z, b.z, h[2], l[2]);
    split2(a.w, b.w, h[3], l[3]);
    const long o = r * (long)cols + c;
    *(uint4*)&H[o] = make_uint4(h[0], h[1], h[2], h[3]);
    *(uint4*)&L[o] = make_uint4(l[0], l[1], l[2], l[3]);
}

// ---------------------------------------------------------------------------
// Generic packed-bf16 GEMM, 128x128 tile, 3-stage cp.async pipeline.
// EPI: 0 = fp32 store to C; 1 = packed-T store; 2 = tanh + packed-T store.
// Operands are direct-layout [kp][col] u32 arrays (h + l).
// ---------------------------------------------------------------------------
template <int EPI>
__global__ __launch_bounds__(256, 2) void gemm_q(
    const unsigned* __restrict__ Ah, const unsigned* __restrict__ Al, long lda, long sA,
    const unsigned* __restrict__ Bh, const unsigned* __restrict__ Bl, long ldb, long sB,
    float* __restrict__ C, long ldc, long sC,
    unsigned* __restrict__ CTh, unsigned* __restrict__ CTl, long ldct, long sCT,
    int K)
{
    extern __shared__ unsigned smp[];
    const int t = threadIdx.x, lane = t & 31, w = t >> 5;
    const int wm = w >> 2, wn = w & 3;
    const int bm = blockIdx.y * 128, bn = blockIdx.x * 128;
    const int z = blockIdx.z;
    const unsigned* Abh = Ah + z * sA + bm;
    const unsigned* Abl = Al + z * sA + bm;
    const unsigned* Bbh = Bh + z * sB + bn;
    const unsigned* Bbl = Bl + z * sB + bn;
    const int nk = K >> 5;

    float acc[4][4][4];
#pragma unroll
    for (int i = 0; i < 4; i++)
#pragma unroll
        for (int j = 0; j < 4; j++)
#pragma unroll
            for (int q = 0; q < 4; q++) acc[i][j][q] = 0.f;

    auto issue = [&](int j, int s) {
        unsigned* st = smp + s * 8192;
        const long ro = (long)(j * 16);
        ld_tile(st,        Abh + ro * lda, lda, t);
        ld_tile(st + 2048, Abl + ro * lda, lda, t);
        ld_tile(st + 4096, Bbh + ro * ldb, ldb, t);
        ld_tile(st + 6144, Bbl + ro * ldb, ldb, t);
        asm volatile("cp.async.commit_group;" ::: "memory");
    };

    issue(0, 0);
    if (nk > 1) issue(1, 1);
    for (int j = 0; j < nk; j++) {
        if (j + 2 < nk) issue(j + 2, (j + 2) % 3);
        if (j + 2 < nk)      asm volatile("cp.async.wait_group 2;" ::: "memory");
        else if (j + 1 < nk) asm volatile("cp.async.wait_group 1;" ::: "memory");
        else                 asm volatile("cp.async.wait_group 0;" ::: "memory");
        __syncthreads();
        warp_compute(smp + (j % 3) * 8192, acc, wm, wn, lane);
        __syncthreads();
    }

    const int r = lane >> 2, c2 = (lane & 3) * 2;
#pragma unroll
    for (int mf = 0; mf < 4; mf++)
#pragma unroll
        for (int nf = 0; nf < 4; nf++) {
            const int row = bm + wm * 64 + mf * 16 + r;
            const int col = bn + wn * 32 + nf * 8 + c2;
            float v0 = acc[mf][nf][0], v1 = acc[mf][nf][1];
            float v2 = acc[mf][nf][2], v3 = acc[mf][nf][3];
            if (EPI == 2) {
                v0 = tanhf(v0); v1 = tanhf(v1); v2 = tanhf(v2); v3 = tanhf(v3);
            }
            if (EPI == 0) {
                *(float2*)&C[z * sC + (long)row * ldc + col] = make_float2(v0, v1);
                *(float2*)&C[z * sC + (long)(row + 8) * ldc + col] = make_float2(v2, v3);
            } else {
                unsigned h0, l0, h1, l1;
                split2(v0, v1, h0, l0);
                split2(v2, v3, h1, l1);
                const long o = z * sCT + (long)(col >> 1) * ldct;
                CTh[o + row] = h0;     CTl[o + row] = l0;
                CTh[o + row + 8] = h1; CTl[o + row + 8] = l1;
            }
        }
}

// ---------------------------------------------------------------------------
// Softmax over 256 cols + write both packed attn layouts:
//  attn_pT[b][pp][h] = pack over p pairs (for alphas-A)
//  attn_hT[b][hp][p] = pack over h pairs (for betas-A)
// ---------------------------------------------------------------------------
__global__ void softmax_pack_kernel(
    const float* __restrict__ E,
    unsigned* __restrict__ APh, unsigned* __restrict__ APl,
    unsigned* __restrict__ AHh, unsigned* __restrict__ AHl)
{
    __shared__ float smr[8][258];
    const int b = blockIdx.x >> 5;
    const int p0 = (blockIdx.x & 31) << 3;
    const int lane = threadIdx.x, ty = threadIdx.y;
    const float* row = E + ((long)b * 256 + p0 + ty) * 256;

    float v[8];
    float mx = -1e30f;
#pragma unroll
    for (int i = 0; i < 8; i++) {
        v[i] = row[i * 32 + lane];
        mx = fmaxf(mx, v[i]);
    }
#pragma unroll
    for (int o = 16; o; o >>= 1) mx = fmaxf(mx, __shfl_xor_sync(0xffffffffu, mx, o));
    float s = 0.f;
#pragma unroll
    for (int i = 0; i < 8; i++) { v[i] = expf(v[i] - mx); s += v[i]; }
#pragma unroll
    for (int o = 16; o; o >>= 1) s += __shfl_xor_sync(0xffffffffu, s, o);
    const float inv = 1.0f / s;
#pragma unroll
    for (int i = 0; i < 8; i++) smr[ty][i * 32 + lane] = v[i] * inv;
    __syncthreads();

    const int t = ty * 32 + lane;
    {   // attn_pT: pack rows (2ppl, 2ppl+1), h contiguous
        const int ppl = t >> 6;
        const int h4 = (t & 63) << 2;
        unsigned h[4], l[4];
#pragma unroll
        for (int q = 0; q < 4; q++)
            split2(smr[2 * ppl][h4 + q], smr[2 * ppl + 1][h4 + q], h[q], l[q]);
        const long o = (long)b * 32768 + (long)((p0 >> 1) + ppl) * 256 + h4;
        *(uint4*)&APh[o] = make_uint4(h[0], h[1], h[2], h[3]);
        *(uint4*)&APl[o] = make_uint4(l[0], l[1], l[2], l[3]);
    }
#pragma unroll
    for (int i = 0; i < 4; i++) {  // attn_hT: pack cols (2hp, 2hp+1) at row p
        const int hp = (t >> 3) + (i << 5);
        const int pl = t & 7;
        unsigned hh, ll;
        split2(smr[pl][2 * hp], smr[pl][2 * hp + 1], hh, ll);
        AHh[(long)b * 32768 + (long)hp * 256 + p0 + pl] = hh;
        AHl[(long)b * 32768 + (long)hp * 256 + p0 + pl] = ll;
    }
}

// ---------------------------------------------------------------------------
// Fused compare: out[b,n] = sum_{p<256} tanh( concat(X1,X2)[b,p,:] @ W[:,n] )
// X1 = PkT/HkT slice (lda 8192, col off b*256), X2 = betasT/alphasT (per-batch
// [512][256]), W = WGT [1024][2048]. 3-stage cp.async pipeline.
// ---------------------------------------------------------------------------
__global__ __launch_bounds__(256, 2) void compare_q(
    const unsigned* __restrict__ X1h, const unsigned* __restrict__ X1l,
    const unsigned* __restrict__ X2h, const unsigned* __restrict__ X2l,
    const unsigned* __restrict__ Wh, const unsigned* __restrict__ Wl,
    float* __restrict__ out)
{
    extern __shared__ unsigned smp[];
    const int t = threadIdx.x, lane = t & 31, w = t >> 5;
    const int wm = w >> 2, wn = w & 3;
    const int z = blockIdx.z;
    const int bn = blockIdx.x * 128;
    const unsigned* Wbh = Wh + bn;
    const unsigned* Wbl = Wl + bn;
    const int nk = 64;

    float csum[4][2];
#pragma unroll
    for (int nf = 0; nf < 4; nf++) { csum[nf][0] = 0.f; csum[nf][1] = 0.f; }

    for (int mt = 0; mt < 256; mt += 128) {
        float acc[4][4][4];
#pragma unroll
        for (int i = 0; i < 4; i++)
#pragma unroll
            for (int j = 0; j < 4; j++)
#pragma unroll
                for (int q = 0; q < 4; q++) acc[i][j][q] = 0.f;

        auto issue = [&](int j, int s) {
            unsigned* st = smp + s * 8192;
            if (j < 32) {
                const long ro = (long)(j * 16) * 8192 + z * 256 + mt;
                ld_tile(st,        X1h + ro, 8192, t);
                ld_tile(st + 2048, X1l + ro, 8192, t);
            } else {
                const long ro = (long)z * 131072 + (long)((j - 32) * 16) * 256 + mt;
                ld_tile(st,        X2h + ro, 256, t);
                ld_tile(st + 2048, X2l + ro, 256, t);
            }
            const long wo = (long)(j * 16) * 2048;
            ld_tile(st + 4096, Wbh + wo, 2048, t);
            ld_tile(st + 6144, Wbl + wo, 2048, t);
            asm volatile("cp.async.commit_group;" ::: "memory");
        };

        issue(0, 0);
        issue(1, 1);
        for (int j = 0; j < nk; j++) {
            if (j + 2 < nk) issue(j + 2, (j + 2) % 3);
            if (j + 2 < nk)      asm volatile("cp.async.wait_group 2;" ::: "memory");
            else if (j + 1 < nk) asm volatile("cp.async.wait_group 1;" ::: "memory");
            else                 asm volatile("cp.async.wait_group 0;" ::: "memory");
            __syncthreads();
            warp_compute(smp + (j % 3) * 8192, acc, wm, wn, lane);
            __syncthreads();
        }
#pragma unroll
        for (int mf = 0; mf < 4; mf++)
#pragma unroll
            for (int nf = 0; nf < 4; nf++) {
                csum[nf][0] += tanhf(acc[mf][nf][0]) + tanhf(acc[mf][nf][2]);
                csum[nf][1] += tanhf(acc[mf][nf][1]) + tanhf(acc[mf][nf][3]);
            }
    }

#pragma unroll
    for (int off = 4; off <= 16; off <<= 1)
#pragma unroll
        for (int nf = 0; nf < 4; nf++) {
            csum[nf][0] += __shfl_xor_sync(0xffffffffu, csum[nf][0], off);
            csum[nf][1] += __shfl_xor_sync(0xffffffffu, csum[nf][1], off);
        }
    float* red = (float*)smp;  // pipeline fully drained; reuse stage memory
    if (lane < 4) {
#pragma unroll
        for (int nf = 0; nf < 4; nf++) {
            red[wm * 128 + wn * 32 + nf * 8 + 2 * lane + 0] = csum[nf][0];
            red[wm * 128 + wn * 32 + nf * 8 + 2 * lane + 1] = csum[nf][1];
        }
    }
    __syncthreads();
    if (t < 128) out[(long)z * 2048 + bn + t] = red[t] + red[128 + t];
}

// ---------------------------------------------------------------------------
// Skinny classifier MLP + final layer (fp32; negligible time).
// ---------------------------------------------------------------------------
__global__ __launch_bounds__(128) void mlp_layer_kernel(
    const float* __restrict__ A1, const float* __restrict__ A2, int ksplit,
    const float* __restrict__ W, const float* __restrict__ bias,
    float* __restrict__ out, int N, int K, int do_tanh)
{
    const int n = blockIdx.x * 128 + threadIdx.x;
    const int m0 = blockIdx.y * 8;

    __shared__ float As[8][129];
    float acc[8];
#pragma unroll
    for (int i = 0; i < 8; i++) acc[i] = 0.f;

    for (int k0 = 0; k0 < K; k0 += 128) {
#pragma unroll
        for (int i = 0; i < 8; i++) {
            const int k = k0 + threadIdx.x;
            As[i][threadIdx.x] = (k < ksplit)
                ? A1[(long)(m0 + i) * ksplit + k]
                : A2[(long)(m0 + i) * ksplit + (k - ksplit)];
        }
        __syncthreads();
        for (int kk = 0; kk < 128; kk++) {
            const float wv = W[(long)(k0 + kk) * N + n];
#pragma unroll
            for (int i = 0; i < 8; i++) acc[i] += As[i][kk] * wv;
        }
        __syncthreads();
    }
    const float bb = bias[n];
#pragma unroll
    for (int i = 0; i < 8; i++) {
        float r = acc[i] + bb;
        out[(long)(m0 + i) * N + n] = do_tanh ? tanhf(r) : r;
    }
}

__global__ void final_layer_kernel(
    const float* __restrict__ A, const float* __restrict__ W3,
    const float* __restrict__ b3, float* __restrict__ out)
{
    const int m = blockIdx.x / 3;
    const int n = blockIdx.x % 3;
    const int lane = threadIdx.x;
    float s = 0.f;
    for (int k = lane; k < 2048; k += 32)
        s += A[(long)m * 2048 + k] * W3[(long)k * 3 + n];
#pragma unroll
    for (int o = 16; o; o >>= 1) s += __shfl_xor_sync(0xffffffffu, s, o);
    if (lane == 0) out[m * 3 + n] = s + b3[n];
}

// ---------------------------------------------------------------------------
extern "C" void kernel_launch(void* const* d_in, const int* in_sizes, int n_in,
                              void* d_out, int out_size)
{
    const float* premises   = (const float*)d_in[0];
    const float* hypotheses = (const float*)d_in[1];
    const float* W_F = (const float*)d_in[2];
    const float* W_G = (const float*)d_in[3];
    const float* W1  = (const float*)d_in[4];
    const float* b1  = (const float*)d_in[5];
    const float* W2  = (const float*)d_in[6];
    const float* b2  = (const float*)d_in[7];
    const float* W3  = (const float*)d_in[8];
    const float* b3  = (const float*)d_in[9];
    float* out = (float*)d_out;

    unsigned* sc = nullptr;
    cudaGetSymbolAddress((void**)&sc, g_scratch);

    const int SMEM = 3 * 8192 * 4;  // 96KB
    cudaFuncSetAttribute(gemm_q<0>, cudaFuncAttributeMaxDynamicSharedMemorySize, SMEM);
    cudaFuncSetAttribute(gemm_q<1>, cudaFuncAttributeMaxDynamicSharedMemorySize, SMEM);
    cudaFuncSetAttribute(gemm_q<2>, cudaFuncAttributeMaxDynamicSharedMemorySize, SMEM);
    cudaFuncSetAttribute(compare_q, cudaFuncAttributeMaxDynamicSharedMemorySize, SMEM);

    float* E  = (float*)(sc + OFF_E);
    float* S1 = (float*)(sc + OFF_S1);
    float* S2 = (float*)(sc + OFF_S2);
    float* a1 = (float*)(sc + OFF_A1);
    float* a2 = (float*)(sc + OFF_A2);

    // ---- pack inputs ----
    pack_kT_kernel<<<dim3(16, 128), 256>>>(premises,   sc + OFF_PKT_H, sc + OFF_PKT_L, 8192, 1024);
    pack_kT_kernel<<<dim3(16, 128), 256>>>(hypotheses, sc + OFF_HKT_H, sc + OFF_HKT_L, 8192, 1024);
    pack_rows_kernel<<<512,  256>>>(W_F, sc + OFF_WFT_H, sc + OFF_WFT_L, 1024, 131072);
    pack_rows_kernel<<<2048, 256>>>(W_G, sc + OFF_WGT_H, sc + OFF_WGT_L, 2048, 524288);
    pack_rows_kernel<<<4096, 256>>>(premises,   sc + OFF_PPT_H, sc + OFF_PPT_L, 1024, 1048576);
    pack_rows_kernel<<<4096, 256>>>(hypotheses, sc + OFF_HPT_H, sc + OFF_HPT_L, 1024, 1048576);

    // ---- projections: Fp/Fh = tanh(X @ W_F), packed-T output ----
    gemm_q<2><<<dim3(8, 64, 1), 256, SMEM>>>(
        sc + OFF_PKT_H, sc + OFF_PKT_L, 8192, 0,
        sc + OFF_WFT_H, sc + OFF_WFT_L, 1024, 0,
        nullptr, 0, 0, sc + OFF_FPT_H, sc + OFF_FPT_L, 8192, 0, 1024);
    gemm_q<2><<<dim3(8, 64, 1), 256, SMEM>>>(
        sc + OFF_HKT_H, sc + OFF_HKT_L, 8192, 0,
        sc + OFF_WFT_H, sc + OFF_WFT_L, 1024, 0,
        nullptr, 0, 0, sc + OFF_FHT_H, sc + OFF_FHT_L, 8192, 0, 1024);

    // ---- E[b] = Fp[b] @ Fh[b]^T (fp32 out) ----
    gemm_q<0><<<dim3(2, 2, 32), 256, SMEM>>>(
        sc + OFF_FPT_H, sc + OFF_FPT_L, 8192, 256,
        sc + OFF_FHT_H, sc + OFF_FHT_L, 8192, 256,
        E, 256, 65536, nullptr, nullptr, 0, 0, 1024);

    // ---- softmax + pack both attn layouts ----
    softmax_pack_kernel<<<1024, dim3(32, 8)>>>(
        E, sc + OFF_ATP_H, sc + OFF_ATP_L, sc + OFF_ATH_H, sc + OFF_ATH_L);

    // ---- betas = attn @ H ; alphas = attn^T @ P (packed-T out) ----
    gemm_q<1><<<dim3(8, 2, 32), 256, SMEM>>>(
        sc + OFF_ATH_H, sc + OFF_ATH_L, 256, 32768,
        sc + OFF_HPT_H, sc + OFF_HPT_L, 1024, 131072,
        nullptr, 0, 0, sc + OFF_BET_H, sc + OFF_BET_L, 256, 131072, 256);
    gemm_q<1><<<dim3(8, 2, 32), 256, SMEM>>>(
        sc + OFF_ATP_H, sc + OFF_ATP_L, 256, 32768,
        sc + OFF_PPT_H, sc + OFF_PPT_L, 1024, 131072,
        nullptr, 0, 0, sc + OFF_ALP_H, sc + OFF_ALP_L, 256, 131072, 256);

    // ---- compare (fused GEMM + tanh + sequence-sum) ----
    compare_q<<<dim3(16, 1, 32), 256, SMEM>>>(
        sc + OFF_PKT_H, sc + OFF_PKT_L, sc + OFF_BET_H, sc + OFF_BET_L,
        sc + OFF_WGT_H, sc + OFF_WGT_L, S1);
    compare_q<<<dim3(16, 1, 32), 256, SMEM>>>(
        sc + OFF_HKT_H, sc + OFF_HKT_L, sc + OFF_ALP_H, sc + OFF_ALP_L,
        sc + OFF_WGT_H, sc + OFF_WGT_L, S2);

    // ---- classifier ----
    mlp_layer_kernel<<<dim3(16, 4), 128>>>(S1, S2, 2048, W1, b1, a1, 2048, 4096, 1);
    mlp_layer_kernel<<<dim3(16, 4), 128>>>(a1, a1, 2048, W2, b2, a2, 2048, 2048, 1);
    final_layer_kernel<<<96, 32>>>(a2, W3, b3, out);
}

// round 8
// speedup vs baseline: 1.6720x; 1.0538x over previous
#include <cuda_runtime.h>
#include <cuda_bf16.h>
#include <math.h>
#include <stdint.h>

// ---------------------------------------------------------------------------
// Decomposable-Attention NLI forward. mma.sync bf16 hi/lo-split GEMMs with
// ldmatrix fragment loads + cp.async double-buffered K64 stages.
// B=32, L=256, D=1024, FF=2048.
// ---------------------------------------------------------------------------

// bf16 scratch offsets (elements)
#define O_PH_H 0L
#define O_PH_L 8388608L
#define O_HH_H 16777216L
#define O_HH_L 25165824L
#define O_FP_H 33554432L
#define O_FP_L 41943040L
#define O_FH_H 50331648L
#define O_FH_L 58720256L
#define O_PT_H 67108864L
#define O_PT_L 75497472L
#define O_HT_H 83886080L
#define O_HT_L 92274688L
#define O_BE_H 100663296L
#define O_BE_L 109051904L
#define O_AL_H 117440512L
#define O_AL_L 125829120L
#define O_WF_H 134217728L
#define O_WF_L 135266304L
#define O_WG_H 136314880L
#define O_WG_L 140509184L
#define O_AT_H 144703488L
#define O_AT_L 146800640L
#define O_TT_H 148897792L
#define O_TT_L 150994944L
#define BF_TOTAL 153092096L
#define OF_E  0L
#define OF_S1 2097152L
#define OF_S2 2162688L
#define OF_A1 2228224L
#define OF_A2 2293760L
#define F32_TOTAL 2359296L

__device__ __align__(1024) __nv_bfloat16 g_bf[BF_TOTAL];
__device__ __align__(1024) float g_f32[F32_TOTAL];

// stage layout (bytes): Ah 32K | Al 32K | Bh 16K | Bl 16K = 96KB; 2 stages
#define ST_AL 32768
#define ST_BH 65536
#define ST_BL 81920
#define ST_SZ 98304

__device__ __forceinline__ uint32_t smem_u32(const void* p) {
    uint32_t a;
    asm("{ .reg .u64 t; cvta.to.shared.u64 t, %1; cvt.u32.u64 %0, t; }" : "=r"(a) : "l"(p));
    return a;
}
__device__ __forceinline__ void split1(float v, __nv_bfloat16& h, __nv_bfloat16& l) {
    h = __float2bfloat16(v);
    l = __float2bfloat16(v - __bfloat162float(h));
}
__device__ __forceinline__ uint32_t pk(__nv_bfloat16 a, __nv_bfloat16 b) {
    return (uint32_t)__bfloat16_as_ushort(a) | ((uint32_t)__bfloat16_as_ushort(b) << 16);
}
__device__ __forceinline__ void mma_bf16(float* c, const uint32_t* a, const uint32_t* b) {
    asm volatile(
        "mma.sync.aligned.m16n8k16.row.col.f32.bf16.bf16.f32 "
        "{%0,%1,%2,%3},{%4,%5,%6,%7},{%8,%9},{%0,%1,%2,%3};\n"
        : "+f"(c[0]), "+f"(c[1]), "+f"(c[2]), "+f"(c[3])
        : "r"(a[0]), "r"(a[1]), "r"(a[2]), "r"(a[3]), "r"(b[0]), "r"(b[1]));
}
__device__ __forceinline__ void ldsm4(uint32_t* r, uint32_t addr) {
    asm volatile("ldmatrix.sync.aligned.m8n8.x4.shared.b16 {%0,%1,%2,%3}, [%4];"
                 : "=r"(r[0]), "=r"(r[1]), "=r"(r[2]), "=r"(r[3]) : "r"(addr));
}

// cp.async ROWS x 64-bf16(128B) SW128 tile; 512 threads
template <int ROWS>
__device__ __forceinline__ void ld_sw128(uint32_t sb, const __nv_bfloat16* g, long ld, int t) {
    constexpr int ITERS = ROWS * 8 / 512;
#pragma unroll
    for (int i = 0; i < ITERS; i++) {
        const int idx = t + i * 512;
        const int r = idx >> 3, c = idx & 7;
        uint32_t dst = sb + r * 128 + ((c ^ (r & 7)) << 4);
        asm volatile("cp.async.cg.shared.global [%0], [%1], 16;"
                     :: "r"(dst), "l"(g + (long)r * ld + c * 8) : "memory");
    }
}

// warp compute over one K64 stage via ldmatrix. warp tile 64(m) x 32(n).
template <int NPROD>
__device__ __forceinline__ void wcompute(uint32_t Ab, uint32_t Bb, float acc[4][4][4],
                                         int wm, int wn, int lane) {
    const int lm = lane & 7, mat = lane >> 3;
    const int rsel = (mat & 1) * 8 + lm;   // row within 16-row frag
    const int csel = mat >> 1;             // chunk offset (0/1)
#pragma unroll
    for (int s = 0; s < 4; s++) {
        const int ch = 2 * s + csel;
        uint32_t bh[4][2], bl[4][2];
#pragma unroll
        for (int nfp = 0; nfp < 2; nfp++) {
            const int rn = wn * 32 + nfp * 16 + rsel;
            const uint32_t off = rn * 128 + ((ch ^ (rn & 7)) << 4);
            uint32_t q[4];
            ldsm4(q, Bb + off);
            bh[nfp * 2][0] = q[0]; bh[nfp * 2 + 1][0] = q[1];
            bh[nfp * 2][1] = q[2]; bh[nfp * 2 + 1][1] = q[3];
            ldsm4(q, Bb + 16384 + off);
            bl[nfp * 2][0] = q[0]; bl[nfp * 2 + 1][0] = q[1];
            bl[nfp * 2][1] = q[2]; bl[nfp * 2 + 1][1] = q[3];
        }
#pragma unroll
        for (int mf = 0; mf < 4; mf++) {
            const int rm = wm * 64 + mf * 16 + rsel;
            const uint32_t off = rm * 128 + ((ch ^ (rm & 7)) << 4);
            uint32_t ah[4], al[4];
            ldsm4(ah, Ab + off);
            ldsm4(al, Ab + ST_AL + off);
#pragma unroll
            for (int nf = 0; nf < 4; nf++) {
                mma_bf16(acc[mf][nf], ah, bh[nf]);
                mma_bf16(acc[mf][nf], ah, bl[nf]);
                mma_bf16(acc[mf][nf], al, bh[nf]);
                if (NPROD == 4) mma_bf16(acc[mf][nf], al, bl[nf]);
            }
        }
    }
}

// ---------------------------------------------------------------------------
// D = A @ B^T. A[m][k], B[n][k] bf16 h/l row-major. Block tile 256x128.
// EPI: 0 = fp32 store; 1 = hi/lo pack store; 2 = tanh + pack store.
// ---------------------------------------------------------------------------
template <int EPI, int NPROD>
__global__ __launch_bounds__(512, 1) void mm(
    const __nv_bfloat16* __restrict__ Ah, const __nv_bfloat16* __restrict__ Al, long lda, long sA,
    const __nv_bfloat16* __restrict__ Bh, const __nv_bfloat16* __restrict__ Bl, long ldb, long sB,
    float* __restrict__ Cf, long ldc, long sC,
    __nv_bfloat16* __restrict__ Oh, __nv_bfloat16* __restrict__ Ol, long ldo, long sO, int K)
{
    extern __shared__ __align__(16) char dsm[];
    const uint32_t base = smem_u32(dsm);
    const int t = threadIdx.x, lane = t & 31, wid = t >> 5;
    const int wm = wid >> 2, wn = wid & 3;
    const int bm = blockIdx.y * 256, bn = blockIdx.x * 128, z = blockIdx.z;

    const __nv_bfloat16* Azh = Ah + z * sA + (long)bm * lda;
    const __nv_bfloat16* Azl = Al + z * sA + (long)bm * lda;
    const __nv_bfloat16* Bzh = Bh + z * sB + (long)bn * ldb;
    const __nv_bfloat16* Bzl = Bl + z * sB + (long)bn * ldb;
    const int ns = K >> 6;

    float acc[4][4][4];
#pragma unroll
    for (int i = 0; i < 4; i++)
#pragma unroll
        for (int j = 0; j < 4; j++)
#pragma unroll
            for (int q = 0; q < 4; q++) acc[i][j][q] = 0.f;

    auto issue = [&](int j, int buf) {
        const uint32_t sb = base + buf * ST_SZ;
        const long ko = (long)j << 6;
        ld_sw128<256>(sb,         Azh + ko, lda, t);
        ld_sw128<256>(sb + ST_AL, Azl + ko, lda, t);
        ld_sw128<128>(sb + ST_BH, Bzh + ko, ldb, t);
        ld_sw128<128>(sb + ST_BL, Bzl + ko, ldb, t);
        asm volatile("cp.async.commit_group;" ::: "memory");
    };

    issue(0, 0);
    if (ns > 1) issue(1, 1);
    for (int j = 0; j < ns; j++) {
        if (j + 1 < ns) asm volatile("cp.async.wait_group 1;" ::: "memory");
        else            asm volatile("cp.async.wait_group 0;" ::: "memory");
        __syncthreads();
        const uint32_t sb = base + (j & 1) * ST_SZ;
        wcompute<NPROD>(sb, sb + ST_BH, acc, wm, wn, lane);
        __syncthreads();
        if (j + 2 < ns) issue(j + 2, j & 1);
    }

    const int r = lane >> 2, c2 = (lane & 3) * 2;
#pragma unroll
    for (int mf = 0; mf < 4; mf++)
#pragma unroll
        for (int nf = 0; nf < 4; nf++) {
            const int row = bm + wm * 64 + mf * 16 + r;
            const int col = bn + wn * 32 + nf * 8 + c2;
            float v0 = acc[mf][nf][0], v1 = acc[mf][nf][1];
            float v2 = acc[mf][nf][2], v3 = acc[mf][nf][3];
            if (EPI == 2) { v0 = tanhf(v0); v1 = tanhf(v1); v2 = tanhf(v2); v3 = tanhf(v3); }
            if (EPI == 0) {
                *(float2*)&Cf[z * sC + (long)row * ldc + col] = make_float2(v0, v1);
                *(float2*)&Cf[z * sC + (long)(row + 8) * ldc + col] = make_float2(v2, v3);
            } else {
                __nv_bfloat16 h0, l0, h1, l1;
                split1(v0, h0, l0); split1(v1, h1, l1);
                const long o0 = z * sO + (long)row * ldo + col;
                *(uint32_t*)&Oh[o0] = pk(h0, h1);
                *(uint32_t*)&Ol[o0] = pk(l0, l1);
                split1(v2, h0, l0); split1(v3, h1, l1);
                const long o1 = z * sO + (long)(row + 8) * ldo + col;
                *(uint32_t*)&Oh[o1] = pk(h0, h1);
                *(uint32_t*)&Ol[o1] = pk(l0, l1);
            }
        }
}

// ---------------------------------------------------------------------------
// Fused compare: S[z,n] = sum_{p<256} tanh( concat(X1,X2)[z,p,:] @ W[:,n] )
// A = 256 rows (all p). K=2048 (X1 for k<1024, X2 for k>=1024). W: [n][2048].
// ---------------------------------------------------------------------------
__global__ __launch_bounds__(512, 1) void mm_compare(
    const __nv_bfloat16* __restrict__ X1h, const __nv_bfloat16* __restrict__ X1l,
    const __nv_bfloat16* __restrict__ X2h, const __nv_bfloat16* __restrict__ X2l,
    const __nv_bfloat16* __restrict__ Wh,  const __nv_bfloat16* __restrict__ Wl,
    float* __restrict__ S)
{
    extern __shared__ __align__(16) char dsm[];
    __shared__ float red[4][128];
    const uint32_t base = smem_u32(dsm);
    const int t = threadIdx.x, lane = t & 31, wid = t >> 5;
    const int wm = wid >> 2, wn = wid & 3;
    const int bn = blockIdx.x * 128, z = blockIdx.z;
    const int ns = 32;

    const __nv_bfloat16* Wbh = Wh + (long)bn * 2048;
    const __nv_bfloat16* Wbl = Wl + (long)bn * 2048;

    float acc[4][4][4];
#pragma unroll
    for (int i = 0; i < 4; i++)
#pragma unroll
        for (int j = 0; j < 4; j++)
#pragma unroll
            for (int q = 0; q < 4; q++) acc[i][j][q] = 0.f;

    auto issue = [&](int j, int buf) {
        const uint32_t sb = base + buf * ST_SZ;
        const __nv_bfloat16* axh;
        const __nv_bfloat16* axl;
        if (j < 16) {
            axh = X1h + (long)z * 262144 + ((long)j << 6);
            axl = X1l + (long)z * 262144 + ((long)j << 6);
        } else {
            axh = X2h + (long)z * 262144 + ((long)(j - 16) << 6);
            axl = X2l + (long)z * 262144 + ((long)(j - 16) << 6);
        }
        ld_sw128<256>(sb,         axh, 1024, t);
        ld_sw128<256>(sb + ST_AL, axl, 1024, t);
        ld_sw128<128>(sb + ST_BH, Wbh + ((long)j << 6), 2048, t);
        ld_sw128<128>(sb + ST_BL, Wbl + ((long)j << 6), 2048, t);
        asm volatile("cp.async.commit_group;" ::: "memory");
    };

    issue(0, 0);
    issue(1, 1);
    for (int j = 0; j < ns; j++) {
        if (j + 1 < ns) asm volatile("cp.async.wait_group 1;" ::: "memory");
        else            asm volatile("cp.async.wait_group 0;" ::: "memory");
        __syncthreads();
        const uint32_t sb = base + (j & 1) * ST_SZ;
        wcompute<3>(sb, sb + ST_BH, acc, wm, wn, lane);
        __syncthreads();
        if (j + 2 < ns) issue(j + 2, j & 1);
    }

    // tanh + sum over this warp's 64 rows
    float csum[4][2];
#pragma unroll
    for (int nf = 0; nf < 4; nf++) { csum[nf][0] = 0.f; csum[nf][1] = 0.f; }
#pragma unroll
    for (int mf = 0; mf < 4; mf++)
#pragma unroll
        for (int nf = 0; nf < 4; nf++) {
            csum[nf][0] += tanhf(acc[mf][nf][0]) + tanhf(acc[mf][nf][2]);
            csum[nf][1] += tanhf(acc[mf][nf][1]) + tanhf(acc[mf][nf][3]);
        }
#pragma unroll
    for (int off = 4; off <= 16; off <<= 1)
#pragma unroll
        for (int nf = 0; nf < 4; nf++) {
            csum[nf][0] += __shfl_xor_sync(0xffffffffu, csum[nf][0], off);
            csum[nf][1] += __shfl_xor_sync(0xffffffffu, csum[nf][1], off);
        }
    if (lane < 4) {
#pragma unroll
        for (int nf = 0; nf < 4; nf++) {
            red[wm][wn * 32 + nf * 8 + 2 * lane + 0] = csum[nf][0];
            red[wm][wn * 32 + nf * 8 + 2 * lane + 1] = csum[nf][1];
        }
    }
    __syncthreads();
    if (t < 128)
        S[(long)z * 2048 + bn + t] = red[0][t] + red[1][t] + red[2][t] + red[3][t];
}

// fp32 row-major -> elementwise bf16 hi/lo (same layout)
__global__ __launch_bounds__(256) void pack_nat(
    const float* __restrict__ X, __nv_bfloat16* __restrict__ H,
    __nv_bfloat16* __restrict__ L, long n4)
{
    const long i = (long)blockIdx.x * 256 + threadIdx.x;
    if (i >= n4) return;
    float4 v = ((const float4*)X)[i];
    __nv_bfloat16 h[4], l[4];
    split1(v.x, h[0], l[0]); split1(v.y, h[1], l[1]);
    split1(v.z, h[2], l[2]); split1(v.w, h[3], l[3]);
    ((uint2*)H)[i] = make_uint2(pk(h[0], h[1]), pk(h[2], h[3]));
    ((uint2*)L)[i] = make_uint2(pk(l[0], l[1]), pk(l[2], l[3]));
}

// fp32 [Z][R][C] -> bf16 hi/lo [Z][C][R]
__global__ __launch_bounds__(256) void pack_T(
    const float* __restrict__ X, __nv_bfloat16* __restrict__ H,
    __nv_bfloat16* __restrict__ L, int R, int C)
{
    __shared__ float tile[32][33];
    const int c0 = blockIdx.x * 32, r0 = blockIdx.y * 32;
    const int tx = threadIdx.x & 31, ty = threadIdx.x >> 5;
    const long zoff = (long)blockIdx.z * R * C;
#pragma unroll
    for (int i = 0; i < 4; i++)
        tile[ty + i * 8][tx] = X[zoff + (long)(r0 + ty + i * 8) * C + c0 + tx];
    __syncthreads();
#pragma unroll
    for (int i = 0; i < 4; i++) {
        const int c = ty + i * 8;
        __nv_bfloat16 h, l;
        split1(tile[tx][c], h, l);
        H[zoff + (long)(c0 + c) * R + r0 + tx] = h;
        L[zoff + (long)(c0 + c) * R + r0 + tx] = l;
    }
}

// softmax over 256 cols; writes attn [b][p][h] and attn^T [b][h][p] hi/lo
__global__ void softmax_pack(
    const float* __restrict__ E,
    __nv_bfloat16* __restrict__ ATh, __nv_bfloat16* __restrict__ ATl,
    __nv_bfloat16* __restrict__ TTh, __nv_bfloat16* __restrict__ TTl)
{
    __shared__ float sm[8][257];
    const int b = blockIdx.x >> 5;
    const int p0 = (blockIdx.x & 31) << 3;
    const int lane = threadIdx.x, ty = threadIdx.y;
    const float* row = E + ((long)b * 256 + p0 + ty) * 256;
    float v[8];
    float mx = -1e30f;
#pragma unroll
    for (int i = 0; i < 8; i++) { v[i] = row[i * 32 + lane]; mx = fmaxf(mx, v[i]); }
#pragma unroll
    for (int o = 16; o; o >>= 1) mx = fmaxf(mx, __shfl_xor_sync(0xffffffffu, mx, o));
    float s = 0.f;
#pragma unroll
    for (int i = 0; i < 8; i++) { v[i] = expf(v[i] - mx); s += v[i]; }
#pragma unroll
    for (int o = 16; o; o >>= 1) s += __shfl_xor_sync(0xffffffffu, s, o);
    const float inv = 1.0f / s;
#pragma unroll
    for (int i = 0; i < 8; i++) sm[ty][i * 32 + lane] = v[i] * inv;
    __syncthreads();
    const int t = ty * 32 + lane;
    {
        const int pr = t >> 5, c0 = (t & 31) << 3;
        uint32_t hw[4], lw[4];
#pragma unroll
        for (int q = 0; q < 4; q++) {
            __nv_bfloat16 h0, l0, h1, l1;
            split1(sm[pr][c0 + 2 * q], h0, l0); split1(sm[pr][c0 + 2 * q + 1], h1, l1);
            hw[q] = pk(h0, h1); lw[q] = pk(l0, l1);
        }
        const long o = ((long)b * 256 + p0 + pr) * 256 + c0;
        *(uint4*)&ATh[o] = make_uint4(hw[0], hw[1], hw[2], hw[3]);
        *(uint4*)&ATl[o] = make_uint4(lw[0], lw[1], lw[2], lw[3]);
    }
    {
        uint32_t hw[4], lw[4];
#pragma unroll
        for (int q = 0; q < 4; q++) {
            __nv_bfloat16 h0, l0, h1, l1;
            split1(sm[2 * q][t], h0, l0); split1(sm[2 * q + 1][t], h1, l1);
            hw[q] = pk(h0, h1); lw[q] = pk(l0, l1);
        }
        const long o = ((long)b * 256 + t) * 256 + p0;
        *(uint4*)&TTh[o] = make_uint4(hw[0], hw[1], hw[2], hw[3]);
        *(uint4*)&TTl[o] = make_uint4(lw[0], lw[1], lw[2], lw[3]);
    }
}

__global__ __launch_bounds__(128) void mlp_layer_kernel(
    const float* __restrict__ A1, const float* __restrict__ A2, int ksplit,
    const float* __restrict__ W, const float* __restrict__ bias,
    float* __restrict__ out, int N, int K, int do_tanh)
{
    const int n = blockIdx.x * 128 + threadIdx.x;
    const int m0 = blockIdx.y * 8;
    __shared__ float As[8][129];
    float acc[8];
#pragma unroll
    for (int i = 0; i < 8; i++) acc[i] = 0.f;
    for (int k0 = 0; k0 < K; k0 += 128) {
#pragma unroll
        for (int i = 0; i < 8; i++) {
            const int k = k0 + threadIdx.x;
            As[i][threadIdx.x] = (k < ksplit)
                ? A1[(long)(m0 + i) * ksplit + k]
                : A2[(long)(m0 + i) * ksplit + (k - ksplit)];
        }
        __syncthreads();
        for (int kk = 0; kk < 128; kk++) {
            const float wv = W[(long)(k0 + kk) * N + n];
#pragma unroll
            for (int i = 0; i < 8; i++) acc[i] += As[i][kk] * wv;
        }
        __syncthreads();
    }
    const float bb = bias[n];
#pragma unroll
    for (int i = 0; i < 8; i++) {
        float r = acc[i] + bb;
        out[(long)(m0 + i) * N + n] = do_tanh ? tanhf(r) : r;
    }
}

__global__ void final_layer_kernel(
    const float* __restrict__ A, const float* __restrict__ W3,
    const float* __restrict__ b3, float* __restrict__ out)
{
    const int m = blockIdx.x / 3, n = blockIdx.x % 3, lane = threadIdx.x;
    float s = 0.f;
    for (int k = lane; k < 2048; k += 32)
        s += A[(long)m * 2048 + k] * W3[(long)k * 3 + n];
#pragma unroll
    for (int o = 16; o; o >>= 1) s += __shfl_xor_sync(0xffffffffu, s, o);
    if (lane == 0) out[m * 3 + n] = s + b3[n];
}

extern "C" void kernel_launch(void* const* d_in, const int* in_sizes, int n_in,
                              void* d_out, int out_size)
{
    const float* P   = (const float*)d_in[0];
    const float* Hy  = (const float*)d_in[1];
    const float* W_F = (const float*)d_in[2];
    const float* W_G = (const float*)d_in[3];
    const float* W1  = (const float*)d_in[4];
    const float* b1  = (const float*)d_in[5];
    const float* W2  = (const float*)d_in[6];
    const float* b2  = (const float*)d_in[7];
    const float* W3  = (const float*)d_in[8];
    const float* b3  = (const float*)d_in[9];
    float* out = (float*)d_out;

    __nv_bfloat16* bf = nullptr;
    float* f32 = nullptr;
    cudaGetSymbolAddress((void**)&bf, g_bf);
    cudaGetSymbolAddress((void**)&f32, g_f32);

    const int SM = 2 * ST_SZ;  // 192KB dynamic
    cudaFuncSetAttribute(mm<0, 4>, cudaFuncAttributeMaxDynamicSharedMemorySize, SM);
    cudaFuncSetAttribute(mm<1, 4>, cudaFuncAttributeMaxDynamicSharedMemorySize, SM);
    cudaFuncSetAttribute(mm<2, 3>, cudaFuncAttributeMaxDynamicSharedMemorySize, SM);
    cudaFuncSetAttribute(mm_compare, cudaFuncAttributeMaxDynamicSharedMemorySize, SM);

    float* E  = f32 + OF_E;
    float* S1 = f32 + OF_S1;
    float* S2 = f32 + OF_S2;
    float* a1 = f32 + OF_A1;
    float* a2 = f32 + OF_A2;

    // packs
    pack_nat<<<8192, 256>>>(P,  bf + O_PH_H, bf + O_PH_L, 2097152);
    pack_nat<<<8192, 256>>>(Hy, bf + O_HH_H, bf + O_HH_L, 2097152);
    pack_T<<<dim3(32, 32, 1), 256>>>(W_F, bf + O_WF_H, bf + O_WF_L, 1024, 1024);
    pack_T<<<dim3(64, 64, 1), 256>>>(W_G, bf + O_WG_H, bf + O_WG_L, 2048, 2048);
    pack_T<<<dim3(32, 8, 32), 256>>>(P,  bf + O_PT_H, bf + O_PT_L, 256, 1024);
    pack_T<<<dim3(32, 8, 32), 256>>>(Hy, bf + O_HT_H, bf + O_HT_L, 256, 1024);

    // projections: Fp/Fh = tanh(X @ W_F). A [8192][1024], B = W_F^T [1024][1024]
    mm<2, 3><<<dim3(8, 32, 1), 512, SM>>>(
        bf + O_PH_H, bf + O_PH_L, 1024, 0, bf + O_WF_H, bf + O_WF_L, 1024, 0,
        nullptr, 0, 0, bf + O_FP_H, bf + O_FP_L, 1024, 0, 1024);
    mm<2, 3><<<dim3(8, 32, 1), 512, SM>>>(
        bf + O_HH_H, bf + O_HH_L, 1024, 0, bf + O_WF_H, bf + O_WF_L, 1024, 0,
        nullptr, 0, 0, bf + O_FH_H, bf + O_FH_L, 1024, 0, 1024);

    // E[b] = Fp[b] @ Fh[b]^T (4-product for precision)
    mm<0, 4><<<dim3(2, 1, 32), 512, SM>>>(
        bf + O_FP_H, bf + O_FP_L, 1024, 262144, bf + O_FH_H, bf + O_FH_L, 1024, 262144,
        E, 256, 65536, nullptr, nullptr, 0, 0, 1024);

    softmax_pack<<<1024, dim3(32, 8)>>>(E, bf + O_AT_H, bf + O_AT_L, bf + O_TT_H, bf + O_TT_L);

    // betas = attn @ H (B = H^T) ; alphas = attn^T @ P (B = P^T)
    mm<1, 4><<<dim3(8, 1, 32), 512, SM>>>(
        bf + O_AT_H, bf + O_AT_L, 256, 65536, bf + O_HT_H, bf + O_HT_L, 256, 262144,
        nullptr, 0, 0, bf + O_BE_H, bf + O_BE_L, 1024, 262144, 256);
    mm<1, 4><<<dim3(8, 1, 32), 512, SM>>>(
        bf + O_TT_H, bf + O_TT_L, 256, 65536, bf + O_PT_H, bf + O_PT_L, 256, 262144,
        nullptr, 0, 0, bf + O_AL_H, bf + O_AL_L, 1024, 262144, 256);

    // compare (fused GEMM + tanh + sequence-sum)
    mm_compare<<<dim3(16, 1, 32), 512, SM>>>(
        bf + O_PH_H, bf + O_PH_L, bf + O_BE_H, bf + O_BE_L, bf + O_WG_H, bf + O_WG_L, S1);
    mm_compare<<<dim3(16, 1, 32), 512, SM>>>(
        bf + O_HH_H, bf + O_HH_L, bf + O_AL_H, bf + O_AL_L, bf + O_WG_H, bf + O_WG_L, S2);

    // classifier
    mlp_layer_kernel<<<dim3(16, 4), 128>>>(S1, S2, 2048, W1, b1, a1, 2048, 4096, 1);
    mlp_layer_kernel<<<dim3(16, 4), 128>>>(a1, a1, 2048, W2, b2, a2, 2048, 2048, 1);
    final_layer_kernel<<<96, 32>>>(a2, W3, b3, out);
}

// round 9
// speedup vs baseline: 1.6907x; 1.0112x over previous
#include <cuda_runtime.h>
#include <cuda_fp16.h>
#include <math.h>
#include <stdint.h>

// ---------------------------------------------------------------------------
// Decomposable-Attention NLI forward. mma.sync fp16 hi/lo-split (3 products)
// GEMMs, ldmatrix fragments, 3-stage single-sync cp.async pipeline.
// B=32, L=256, D=1024, FF=2048.
// ---------------------------------------------------------------------------

// fp16 scratch offsets (elements)
#define O_PH_H 0L
#define O_PH_L 8388608L
#define O_HH_H 16777216L
#define O_HH_L 25165824L
#define O_FP_H 33554432L
#define O_FP_L 41943040L
#define O_FH_H 50331648L
#define O_FH_L 58720256L
#define O_PT_H 67108864L
#define O_PT_L 75497472L
#define O_HT_H 83886080L
#define O_HT_L 92274688L
#define O_BE_H 100663296L
#define O_BE_L 109051904L
#define O_AL_H 117440512L
#define O_AL_L 125829120L
#define O_WF_H 134217728L
#define O_WF_L 135266304L
#define O_WG_H 136314880L
#define O_WG_L 140509184L
#define O_AT_H 144703488L
#define O_AT_L 146800640L
#define O_TT_H 148897792L
#define O_TT_L 150994944L
#define BF_TOTAL 153092096L
#define OF_E  0L
#define OF_S1 2097152L
#define OF_S2 2162688L
#define OF_A1 2228224L
#define OF_A2 2293760L
#define F32_TOTAL 2359296L

__device__ __align__(1024) __half g_hf[BF_TOTAL];
__device__ __align__(1024) float g_f32[F32_TOTAL];

// stage layout (bytes): Ah 16K | Al 16K | Bh 16K | Bl 16K = 64KB; 3 stages
#define ST_AL 16384
#define ST_BH 32768
#define ST_BL 49152
#define ST_SZ 65536

__device__ __forceinline__ uint32_t smem_u32(const void* p) {
    uint32_t a;
    asm("{ .reg .u64 t; cvta.to.shared.u64 t, %1; cvt.u32.u64 %0, t; }" : "=r"(a) : "l"(p));
    return a;
}
__device__ __forceinline__ void split1(float v, __half& h, __half& l) {
    h = __float2half_rn(v);
    l = __float2half_rn(v - __half2float(h));
}
__device__ __forceinline__ uint32_t pk(__half a, __half b) {
    return (uint32_t)__half_as_ushort(a) | ((uint32_t)__half_as_ushort(b) << 16);
}
__device__ __forceinline__ void mma_f16(float* c, const uint32_t* a, const uint32_t* b) {
    asm volatile(
        "mma.sync.aligned.m16n8k16.row.col.f32.f16.f16.f32 "
        "{%0,%1,%2,%3},{%4,%5,%6,%7},{%8,%9},{%0,%1,%2,%3};\n"
        : "+f"(c[0]), "+f"(c[1]), "+f"(c[2]), "+f"(c[3])
        : "r"(a[0]), "r"(a[1]), "r"(a[2]), "r"(a[3]), "r"(b[0]), "r"(b[1]));
}
__device__ __forceinline__ void ldsm4(uint32_t* r, uint32_t addr) {
    asm volatile("ldmatrix.sync.aligned.m8n8.x4.shared.b16 {%0,%1,%2,%3}, [%4];"
                 : "=r"(r[0]), "=r"(r[1]), "=r"(r[2]), "=r"(r[3]) : "r"(addr));
}

// cp.async a 128-row x 64-fp16(128B) SW128 tile; 256 threads
__device__ __forceinline__ void ld_sw128(uint32_t sb, const __half* g, long ld, int t) {
#pragma unroll
    for (int i = 0; i < 4; i++) {
        const int idx = t + i * 256;
        const int r = idx >> 3, c = idx & 7;
        uint32_t dst = sb + r * 128 + ((c ^ (r & 7)) << 4);
        asm volatile("cp.async.cg.shared.global [%0], [%1], 16;"
                     :: "r"(dst), "l"(g + (long)r * ld + c * 8) : "memory");
    }
}

// warp compute over one K64 stage. warp tile 64(m) x 32(n); 3 split products.
__device__ __forceinline__ void wcompute(uint32_t Ab, uint32_t Bb, float acc[4][4][4],
                                         int wm, int wn, int lane) {
    const int lm = lane & 7, mat = lane >> 3;
    const int rsel = (mat & 1) * 8 + lm;   // row within 16-row frag
    const int csel = mat >> 1;             // 16B chunk offset (0/1)
#pragma unroll
    for (int s = 0; s < 4; s++) {
        const int ch = 2 * s + csel;
        uint32_t bh[4][2], bl[4][2];
#pragma unroll
        for (int nfp = 0; nfp < 2; nfp++) {
            const int rn = wn * 32 + nfp * 16 + rsel;
            const uint32_t off = rn * 128 + ((ch ^ (rn & 7)) << 4);
            uint32_t q[4];
            ldsm4(q, Bb + off);
            bh[nfp * 2][0] = q[0]; bh[nfp * 2 + 1][0] = q[1];
            bh[nfp * 2][1] = q[2]; bh[nfp * 2 + 1][1] = q[3];
            ldsm4(q, Bb + 16384 + off);
            bl[nfp * 2][0] = q[0]; bl[nfp * 2 + 1][0] = q[1];
            bl[nfp * 2][1] = q[2]; bl[nfp * 2 + 1][1] = q[3];
        }
#pragma unroll
        for (int mf = 0; mf < 4; mf++) {
            const int rm = wm * 64 + mf * 16 + rsel;
            const uint32_t off = rm * 128 + ((ch ^ (rm & 7)) << 4);
            uint32_t ah[4], al[4];
            ldsm4(ah, Ab + off);
            ldsm4(al, Ab + ST_AL + off);
#pragma unroll
            for (int nf = 0; nf < 4; nf++) {
                mma_f16(acc[mf][nf], ah, bh[nf]);
                mma_f16(acc[mf][nf], ah, bl[nf]);
                mma_f16(acc[mf][nf], al, bh[nf]);
            }
        }
    }
}

// ---------------------------------------------------------------------------
// D = A @ B^T. A[m][k], B[n][k] fp16 h/l row-major. Block tile 128x128,
// 256 threads (8 warps 2x4), 3-stage single-sync pipeline.
// EPI: 0 = fp32 store; 1 = hi/lo pack store; 2 = tanh + pack store.
// ---------------------------------------------------------------------------
template <int EPI>
__global__ __launch_bounds__(256, 1) void mm(
    const __half* __restrict__ Ah, const __half* __restrict__ Al, long lda, long sA,
    const __half* __restrict__ Bh, const __half* __restrict__ Bl, long ldb, long sB,
    float* __restrict__ Cf, long ldc, long sC,
    __half* __restrict__ Oh, __half* __restrict__ Ol, long ldo, long sO, int K)
{
    extern __shared__ __align__(16) char dsm[];
    const uint32_t base = smem_u32(dsm);
    const int t = threadIdx.x, lane = t & 31, wid = t >> 5;
    const int wm = wid >> 2, wn = wid & 3;
    const int bm = blockIdx.y * 128, bn = blockIdx.x * 128, z = blockIdx.z;

    const __half* Azh = Ah + z * sA + (long)bm * lda;
    const __half* Azl = Al + z * sA + (long)bm * lda;
    const __half* Bzh = Bh + z * sB + (long)bn * ldb;
    const __half* Bzl = Bl + z * sB + (long)bn * ldb;
    const int ns = K >> 6;

    float acc[4][4][4];
#pragma unroll
    for (int i = 0; i < 4; i++)
#pragma unroll
        for (int j = 0; j < 4; j++)
#pragma unroll
            for (int q = 0; q < 4; q++) acc[i][j][q] = 0.f;

    auto issue = [&](int j, int buf) {
        const uint32_t sb = base + buf * ST_SZ;
        const long ko = (long)j << 6;
        ld_sw128(sb,         Azh + ko, lda, t);
        ld_sw128(sb + ST_AL, Azl + ko, lda, t);
        ld_sw128(sb + ST_BH, Bzh + ko, ldb, t);
        ld_sw128(sb + ST_BL, Bzl + ko, ldb, t);
        asm volatile("cp.async.commit_group;" ::: "memory");
    };

    issue(0, 0);
    issue(1, 1);
    for (int j = 0; j < ns; j++) {
        if (j + 1 < ns) asm volatile("cp.async.wait_group 1;" ::: "memory");
        else            asm volatile("cp.async.wait_group 0;" ::: "memory");
        __syncthreads();
        const uint32_t sb = base + (j % 3) * ST_SZ;
        wcompute(sb, sb + ST_BH, acc, wm, wn, lane);
        if (j + 2 < ns) issue(j + 2, (j + 2) % 3);
    }

    const int r = lane >> 2, c2 = (lane & 3) * 2;
#pragma unroll
    for (int mf = 0; mf < 4; mf++)
#pragma unroll
        for (int nf = 0; nf < 4; nf++) {
            const int row = bm + wm * 64 + mf * 16 + r;
            const int col = bn + wn * 32 + nf * 8 + c2;
            float v0 = acc[mf][nf][0], v1 = acc[mf][nf][1];
            float v2 = acc[mf][nf][2], v3 = acc[mf][nf][3];
            if (EPI == 2) { v0 = tanhf(v0); v1 = tanhf(v1); v2 = tanhf(v2); v3 = tanhf(v3); }
            if (EPI == 0) {
                *(float2*)&Cf[z * sC + (long)row * ldc + col] = make_float2(v0, v1);
                *(float2*)&Cf[z * sC + (long)(row + 8) * ldc + col] = make_float2(v2, v3);
            } else {
                __half h0, l0, h1, l1;
                split1(v0, h0, l0); split1(v1, h1, l1);
                const long o0 = z * sO + (long)row * ldo + col;
                *(uint32_t*)&Oh[o0] = pk(h0, h1);
                *(uint32_t*)&Ol[o0] = pk(l0, l1);
                split1(v2, h0, l0); split1(v3, h1, l1);
                const long o1 = z * sO + (long)(row + 8) * ldo + col;
                *(uint32_t*)&Oh[o1] = pk(h0, h1);
                *(uint32_t*)&Ol[o1] = pk(l0, l1);
            }
        }
}

// ---------------------------------------------------------------------------
// Fused compare: S[z,n] = sum_{p<256} tanh( concat(X1,X2)[z,p,:] @ W[:,n] )
// Two 128-row m-tiles sequential in-kernel; K=2048 (X1 k<1024, X2 k>=1024).
// ---------------------------------------------------------------------------
__global__ __launch_bounds__(256, 1) void mm_compare(
    const __half* __restrict__ X1h, const __half* __restrict__ X1l,
    const __half* __restrict__ X2h, const __half* __restrict__ X2l,
    const __half* __restrict__ Wh,  const __half* __restrict__ Wl,
    float* __restrict__ S)
{
    extern __shared__ __align__(16) char dsm[];
    __shared__ float red[2][128];
    const uint32_t base = smem_u32(dsm);
    const int t = threadIdx.x, lane = t & 31, wid = t >> 5;
    const int wm = wid >> 2, wn = wid & 3;
    const int bn = blockIdx.x * 128, z = blockIdx.z;

    const __half* Wbh = Wh + (long)bn * 2048;
    const __half* Wbl = Wl + (long)bn * 2048;

    float csum[4][2];
#pragma unroll
    for (int nf = 0; nf < 4; nf++) { csum[nf][0] = 0.f; csum[nf][1] = 0.f; }

    for (int mt = 0; mt < 2; mt++) {
        float acc[4][4][4];
#pragma unroll
        for (int i = 0; i < 4; i++)
#pragma unroll
            for (int j = 0; j < 4; j++)
#pragma unroll
                for (int q = 0; q < 4; q++) acc[i][j][q] = 0.f;

        auto issue = [&](int j, int buf) {
            const uint32_t sb = base + buf * ST_SZ;
            const __half* axh;
            const __half* axl;
            const long ro = (long)z * 262144 + (long)mt * 131072;
            if (j < 16) {
                axh = X1h + ro + ((long)j << 6);
                axl = X1l + ro + ((long)j << 6);
            } else {
                axh = X2h + ro + ((long)(j - 16) << 6);
                axl = X2l + ro + ((long)(j - 16) << 6);
            }
            ld_sw128(sb,         axh, 1024, t);
            ld_sw128(sb + ST_AL, axl, 1024, t);
            ld_sw128(sb + ST_BH, Wbh + ((long)j << 6), 2048, t);
            ld_sw128(sb + ST_BL, Wbl + ((long)j << 6), 2048, t);
            asm volatile("cp.async.commit_group;" ::: "memory");
        };

        issue(0, 0);
        issue(1, 1);
        for (int j = 0; j < 32; j++) {
            if (j + 1 < 32) asm volatile("cp.async.wait_group 1;" ::: "memory");
            else            asm volatile("cp.async.wait_group 0;" ::: "memory");
            __syncthreads();
            const uint32_t sb = base + (j % 3) * ST_SZ;
            wcompute(sb, sb + ST_BH, acc, wm, wn, lane);
            if (j + 2 < 32) issue(j + 2, (j + 2) % 3);
        }
#pragma unroll
        for (int mf = 0; mf < 4; mf++)
#pragma unroll
            for (int nf = 0; nf < 4; nf++) {
                csum[nf][0] += tanhf(acc[mf][nf][0]) + tanhf(acc[mf][nf][2]);
                csum[nf][1] += tanhf(acc[mf][nf][1]) + tanhf(acc[mf][nf][3]);
            }
        __syncthreads();  // all warps done with buffers before next m-tile refill
    }

#pragma unroll
    for (int off = 4; off <= 16; off <<= 1)
#pragma unroll
        for (int nf = 0; nf < 4; nf++) {
            csum[nf][0] += __shfl_xor_sync(0xffffffffu, csum[nf][0], off);
            csum[nf][1] += __shfl_xor_sync(0xffffffffu, csum[nf][1], off);
        }
    if (lane < 4) {
#pragma unroll
        for (int nf = 0; nf < 4; nf++) {
            red[wm][wn * 32 + nf * 8 + 2 * lane + 0] = csum[nf][0];
            red[wm][wn * 32 + nf * 8 + 2 * lane + 1] = csum[nf][1];
        }
    }
    __syncthreads();
    if (t < 128)
        S[(long)z * 2048 + bn + t] = red[0][t] + red[1][t];
}

// fp32 row-major -> elementwise fp16 hi/lo (same layout); two tensors via grid.y
__global__ __launch_bounds__(256) void pack_nat2(
    const float* __restrict__ X0, const float* __restrict__ X1,
    __half* __restrict__ H0, __half* __restrict__ L0,
    __half* __restrict__ H1, __half* __restrict__ L1, long n4)
{
    const long i = (long)blockIdx.x * 256 + threadIdx.x;
    if (i >= n4) return;
    const float* X = blockIdx.y ? X1 : X0;
    __half* H = blockIdx.y ? H1 : H0;
    __half* L = blockIdx.y ? L1 : L0;
    float4 v = ((const float4*)X)[i];
    __half h[4], l[4];
    split1(v.x, h[0], l[0]); split1(v.y, h[1], l[1]);
    split1(v.z, h[2], l[2]); split1(v.w, h[3], l[3]);
    ((uint2*)H)[i] = make_uint2(pk(h[0], h[1]), pk(h[2], h[3]));
    ((uint2*)L)[i] = make_uint2(pk(l[0], l[1]), pk(l[2], l[3]));
}

// fp32 [Z][R][C] -> fp16 hi/lo [Z][C][R]
__global__ __launch_bounds__(256) void pack_T(
    const float* __restrict__ X, __half* __restrict__ H,
    __half* __restrict__ L, int R, int C)
{
    __shared__ float tile[32][33];
    const int c0 = blockIdx.x * 32, r0 = blockIdx.y * 32;
    const int tx = threadIdx.x & 31, ty = threadIdx.x >> 5;
    const long zoff = (long)blockIdx.z * R * C;
#pragma unroll
    for (int i = 0; i < 4; i++)
        tile[ty + i * 8][tx] = X[zoff + (long)(r0 + ty + i * 8) * C + c0 + tx];
    __syncthreads();
#pragma unroll
    for (int i = 0; i < 4; i++) {
        const int c = ty + i * 8;
        __half h, l;
        split1(tile[tx][c], h, l);
        H[zoff + (long)(c0 + c) * R + r0 + tx] = h;
        L[zoff + (long)(c0 + c) * R + r0 + tx] = l;
    }
}

// softmax over 256 cols; writes attn [b][p][h] and attn^T [b][h][p] hi/lo
__global__ void softmax_pack(
    const float* __restrict__ E,
    __half* __restrict__ ATh, __half* __restrict__ ATl,
    __half* __restrict__ TTh, __half* __restrict__ TTl)
{
    __shared__ float sm[8][257];
    const int b = blockIdx.x >> 5;
    const int p0 = (blockIdx.x & 31) << 3;
    const int lane = threadIdx.x, ty = threadIdx.y;
    const float* row = E + ((long)b * 256 + p0 + ty) * 256;
    float v[8];
    float mx = -1e30f;
#pragma unroll
    for (int i = 0; i < 8; i++) { v[i] = row[i * 32 + lane]; mx = fmaxf(mx, v[i]); }
#pragma unroll
    for (int o = 16; o; o >>= 1) mx = fmaxf(mx, __shfl_xor_sync(0xffffffffu, mx, o));
    float s = 0.f;
#pragma unroll
    for (int i = 0; i < 8; i++) { v[i] = expf(v[i] - mx); s += v[i]; }
#pragma unroll
    for (int o = 16; o; o >>= 1) s += __shfl_xor_sync(0xffffffffu, s, o);
    const float inv = 1.0f / s;
#pragma unroll
    for (int i = 0; i < 8; i++) sm[ty][i * 32 + lane] = v[i] * inv;
    __syncthreads();
    const int t = ty * 32 + lane;
    {
        const int pr = t >> 5, c0 = (t & 31) << 3;
        uint32_t hw[4], lw[4];
#pragma unroll
        for (int q = 0; q < 4; q++) {
            __half h0, l0, h1, l1;
            split1(sm[pr][c0 + 2 * q], h0, l0); split1(sm[pr][c0 + 2 * q + 1], h1, l1);
            hw[q] = pk(h0, h1); lw[q] = pk(l0, l1);
        }
        const long o = ((long)b * 256 + p0 + pr) * 256 + c0;
        *(uint4*)&ATh[o] = make_uint4(hw[0], hw[1], hw[2], hw[3]);
        *(uint4*)&ATl[o] = make_uint4(lw[0], lw[1], lw[2], lw[3]);
    }
    {
        uint32_t hw[4], lw[4];
#pragma unroll
        for (int q = 0; q < 4; q++) {
            __half h0, l0, h1, l1;
            split1(sm[2 * q][t], h0, l0); split1(sm[2 * q + 1][t], h1, l1);
            hw[q] = pk(h0, h1); lw[q] = pk(l0, l1);
        }
        const long o = ((long)b * 256 + t) * 256 + p0;
        *(uint4*)&TTh[o] = make_uint4(hw[0], hw[1], hw[2], hw[3]);
        *(uint4*)&TTl[o] = make_uint4(lw[0], lw[1], lw[2], lw[3]);
    }
}

__global__ __launch_bounds__(128) void mlp_layer_kernel(
    const float* __restrict__ A1, const float* __restrict__ A2, int ksplit,
    const float* __restrict__ W, const float* __restrict__ bias,
    float* __restrict__ out, int N, int K, int do_tanh)
{
    const int n = blockIdx.x * 128 + threadIdx.x;
    const int m0 = blockIdx.y * 8;
    __shared__ float As[8][129];
    float acc[8];
#pragma unroll
    for (int i = 0; i < 8; i++) acc[i] = 0.f;
    for (int k0 = 0; k0 < K; k0 += 128) {
#pragma unroll
        for (int i = 0; i < 8; i++) {
            const int k = k0 + threadIdx.x;
            As[i][threadIdx.x] = (k < ksplit)
                ? A1[(long)(m0 + i) * ksplit + k]
                : A2[(long)(m0 + i) * ksplit + (k - ksplit)];
        }
        __syncthreads();
        for (int kk = 0; kk < 128; kk++) {
            const float wv = W[(long)(k0 + kk) * N + n];
#pragma unroll
            for (int i = 0; i < 8; i++) acc[i] += As[i][kk] * wv;
        }
        __syncthreads();
    }
    const float bb = bias[n];
#pragma unroll
    for (int i = 0; i < 8; i++) {
        float r = acc[i] + bb;
        out[(long)(m0 + i) * N + n] = do_tanh ? tanhf(r) : r;
    }
}

__global__ void final_layer_kernel(
    const float* __restrict__ A, const float* __restrict__ W3,
    const float* __restrict__ b3, float* __restrict__ out)
{
    const int m = blockIdx.x / 3, n = blockIdx.x % 3, lane = threadIdx.x;
    float s = 0.f;
    for (int k = lane; k < 2048; k += 32)
        s += A[(long)m * 2048 + k] * W3[(long)k * 3 + n];
#pragma unroll
    for (int o = 16; o; o >>= 1) s += __shfl_xor_sync(0xffffffffu, s, o);
    if (lane == 0) out[m * 3 + n] = s + b3[n];
}

extern "C" void kernel_launch(void* const* d_in, const int* in_sizes, int n_in,
                              void* d_out, int out_size)
{
    const float* P   = (const float*)d_in[0];
    const float* Hy  = (const float*)d_in[1];
    const float* W_F = (const float*)d_in[2];
    const float* W_G = (const float*)d_in[3];
    const float* W1  = (const float*)d_in[4];
    const float* b1  = (const float*)d_in[5];
    const float* W2  = (const float*)d_in[6];
    const float* b2  = (const float*)d_in[7];
    const float* W3  = (const float*)d_in[8];
    const float* b3  = (const float*)d_in[9];
    float* out = (float*)d_out;

    __half* hf = nullptr;
    float* f32 = nullptr;
    cudaGetSymbolAddress((void**)&hf, g_hf);
    cudaGetSymbolAddress((void**)&f32, g_f32);

    const int SM = 3 * ST_SZ;  // 192KB dynamic
    cudaFuncSetAttribute(mm<0>, cudaFuncAttributeMaxDynamicSharedMemorySize, SM);
    cudaFuncSetAttribute(mm<1>, cudaFuncAttributeMaxDynamicSharedMemorySize, SM);
    cudaFuncSetAttribute(mm<2>, cudaFuncAttributeMaxDynamicSharedMemorySize, SM);
    cudaFuncSetAttribute(mm_compare, cudaFuncAttributeMaxDynamicSharedMemorySize, SM);

    float* E  = f32 + OF_E;
    float* S1 = f32 + OF_S1;
    float* S2 = f32 + OF_S2;
    float* a1 = f32 + OF_A1;
    float* a2 = f32 + OF_A2;

    // 5 pack launches (0-4) so launch #5 = projection GEMM (ncu -s 5 -c 1)
    pack_nat2<<<dim3(8192, 2), 256>>>(P, Hy, hf + O_PH_H, hf + O_PH_L,
                                      hf + O_HH_H, hf + O_HH_L, 2097152);
    pack_T<<<dim3(32, 32, 1), 256>>>(W_F, hf + O_WF_H, hf + O_WF_L, 1024, 1024);
    pack_T<<<dim3(64, 64, 1), 256>>>(W_G, hf + O_WG_H, hf + O_WG_L, 2048, 2048);
    pack_T<<<dim3(32, 8, 32), 256>>>(P,  hf + O_PT_H, hf + O_PT_L, 256, 1024);
    pack_T<<<dim3(32, 8, 32), 256>>>(Hy, hf + O_HT_H, hf + O_HT_L, 256, 1024);

    // projections: Fp/Fh = tanh(X @ W_F). A [8192][1024], B = W_F^T [1024][1024]
    mm<2><<<dim3(8, 64, 1), 256, SM>>>(
        hf + O_PH_H, hf + O_PH_L, 1024, 0, hf + O_WF_H, hf + O_WF_L, 1024, 0,
        nullptr, 0, 0, hf + O_FP_H, hf + O_FP_L, 1024, 0, 1024);
    mm<2><<<dim3(8, 64, 1), 256, SM>>>(
        hf + O_HH_H, hf + O_HH_L, 1024, 0, hf + O_WF_H, hf + O_WF_L, 1024, 0,
        nullptr, 0, 0, hf + O_FH_H, hf + O_FH_L, 1024, 0, 1024);

    // E[b] = Fp[b] @ Fh[b]^T
    mm<0><<<dim3(2, 2, 32), 256, SM>>>(
        hf + O_FP_H, hf + O_FP_L, 1024, 262144, hf + O_FH_H, hf + O_FH_L, 1024, 262144,
        E, 256, 65536, nullptr, nullptr, 0, 0, 1024);

    softmax_pack<<<1024, dim3(32, 8)>>>(E, hf + O_AT_H, hf + O_AT_L, hf + O_TT_H, hf + O_TT_L);

    // betas = attn @ H (B = H^T) ; alphas = attn^T @ P (B = P^T)
    mm<1><<<dim3(8, 2, 32), 256, SM>>>(
        hf + O_AT_H, hf + O_AT_L, 256, 65536, hf + O_HT_H, hf + O_HT_L, 256, 262144,
        nullptr, 0, 0, hf + O_BE_H, hf + O_BE_L, 1024, 262144, 256);
    mm<1><<<dim3(8, 2, 32), 256, SM>>>(
        hf + O_TT_H, hf + O_TT_L, 256, 65536, hf + O_PT_H, hf + O_PT_L, 256, 262144,
        nullptr, 0, 0, hf + O_AL_H, hf + O_AL_L, 1024, 262144, 256);

    // compare (fused GEMM + tanh + sequence-sum)
    mm_compare<<<dim3(16, 1, 32), 256, SM>>>(
        hf + O_PH_H, hf + O_PH_L, hf + O_BE_H, hf + O_BE_L, hf + O_WG_H, hf + O_WG_L, S1);
    mm_compare<<<dim3(16, 1, 32), 256, SM>>>(
        hf + O_HH_H, hf + O_HH_L, hf + O_AL_H, hf + O_AL_L, hf + O_WG_H, hf + O_WG_L, S2);

    // classifier
    mlp_layer_kernel<<<dim3(16, 4), 128>>>(S1, S2, 2048, W1, b1, a1, 2048, 4096, 1);
    mlp_layer_kernel<<<dim3(16, 4), 128>>>(a1, a1, 2048, W2, b2, a2, 2048, 2048, 1);
    final_layer_kernel<<<96, 32>>>(a2, W3, b3, out);
}